// round 12
// baseline (speedup 1.0000x reference)
#include <cuda_runtime.h>
#include <cuda_bf16.h>
#include <math.h>

#define TOK 2048
#define HIDN 2048
#define KVD 512
#define CHK 64
#define NGC 512
#define NACH 128

__device__ float g_q[TOK * HIDN];
__device__ float g_k[TOK * KVD];
__device__ float g_v[TOK * KVD];
__device__ float g_ql[TOK * HIDN];
__device__ float g_kl[TOK * KVD];
__device__ float g_bt[TOK * KVD];
__device__ float g_A[NACH * CHK * CHK];
__device__ float g_P[NGC * CHK * CHK];
__device__ float g_comb[TOK * HIDN];
__device__ __nv_bfloat16 g_M[(size_t)NACH * 128 * CHK * CHK];  // plain M (diag = 1 exact)
__device__ float g_S0T[(size_t)NGC * 128 * 128];   // [gc][k][c]
__device__ float g_U[(size_t)NGC * CHK * 128];     // [gc][t][c]

__device__ __forceinline__ unsigned f2tf(float x) {
    unsigned u; asm("cvt.rna.tf32.f32 %0, %1;" : "=r"(u) : "f"(x)); return u;
}
__device__ __forceinline__ float f2tf_f(float x) { return __uint_as_float(f2tf(x)); }

__device__ __forceinline__ void mma8(float c[4], const unsigned a[4], const unsigned b[2]) {
    asm volatile(
        "mma.sync.aligned.m16n8k8.row.col.f32.tf32.tf32.f32 "
        "{%0,%1,%2,%3}, {%4,%5,%6,%7}, {%8,%9}, {%0,%1,%2,%3};"
        : "+f"(c[0]), "+f"(c[1]), "+f"(c[2]), "+f"(c[3])
        : "r"(a[0]), "r"(a[1]), "r"(a[2]), "r"(a[3]), "r"(b[0]), "r"(b[1]));
}
__device__ __forceinline__ void cpa16(void* dst, const void* src) {
    unsigned d = (unsigned)__cvta_generic_to_shared(dst);
    asm volatile("cp.async.ca.shared.global [%0], [%1], 16;" :: "r"(d), "l"(src) : "memory");
}
__device__ __forceinline__ void cpa4(void* dst, const void* src) {
    unsigned d = (unsigned)__cvta_generic_to_shared(dst);
    asm volatile("cp.async.ca.shared.global [%0], [%1], 4;" :: "r"(d), "l"(src) : "memory");
}
#define CPA_COMMIT() asm volatile("cp.async.commit_group;" ::: "memory")
#define CPA_WAIT1()  asm volatile("cp.async.wait_group 1;" ::: "memory")

// ------------------------ tf32 MMA GEMM (unchanged) -------------------------
#define GAS 36
#define GBS 136
#define GSTG (128 * GAS + 32 * GBS)

__device__ __forceinline__ void gemm_issue(
    const float* __restrict__ A, const float* __restrict__ B,
    float* As, float* Bs, int bRow, int bCol, int k0, int K, int N, int tid)
{
#pragma unroll
    for (int i = 0; i < 4; i++) {
        int lin = tid + 256 * i;
        int r = lin >> 3, c4 = (lin & 7) << 2;
        cpa16(As + r * GAS + c4, A + (size_t)(bRow + r) * K + k0 + c4);
    }
#pragma unroll
    for (int i = 0; i < 4; i++) {
        int lin = tid + 256 * i;
        int r = lin >> 5, c4 = (lin & 31) << 2;
        cpa16(Bs + r * GBS + c4, B + (size_t)(k0 + r) * N + bCol + c4);
    }
    CPA_COMMIT();
}

__global__ void __launch_bounds__(256) mma_gemm(
    const float* __restrict__ A, const float* __restrict__ B,
    float* __restrict__ C, int M, int N, int K)
{
    extern __shared__ float gsm[];
    const int tid = threadIdx.x, lane = tid & 31, warp = tid >> 5;
    const int bRow = blockIdx.y * 128, bCol = blockIdx.x * 128;
    const int wr = (warp >> 2) * 64, wc = (warp & 3) * 32;
    float acc[4][4][4];
#pragma unroll
    for (int mt = 0; mt < 4; mt++)
#pragma unroll
        for (int nt = 0; nt < 4; nt++)
#pragma unroll
            for (int i = 0; i < 4; i++) acc[mt][nt][i] = 0.f;

    gemm_issue(A, B, gsm, gsm + 128 * GAS, bRow, bCol, 0, K, N, tid);
    gemm_issue(A, B, gsm + GSTG, gsm + GSTG + 128 * GAS, bRow, bCol, 32, K, N, tid);

    const int iters = K / 32;
    for (int it = 0; it < iters; it++) {
        CPA_WAIT1();
        __syncthreads();
        float* As = gsm + (it & 1) * GSTG;
        float* Bs = As + 128 * GAS;
#pragma unroll
        for (int kk = 0; kk < 4; kk++) {
            unsigned a[4][4], bfr[4][2];
            const int kc = kk * 8 + (lane & 3);
            const int r0 = wr + (lane >> 2);
#pragma unroll
            for (int mt = 0; mt < 4; mt++) {
                a[mt][0] = f2tf(As[(r0 + mt * 16) * GAS + kc]);
                a[mt][1] = f2tf(As[(r0 + mt * 16 + 8) * GAS + kc]);
                a[mt][2] = f2tf(As[(r0 + mt * 16) * GAS + kc + 4]);
                a[mt][3] = f2tf(As[(r0 + mt * 16 + 8) * GAS + kc + 4]);
            }
            const int nc0 = wc + (lane >> 2);
#pragma unroll
            for (int nt = 0; nt < 4; nt++) {
                bfr[nt][0] = f2tf(Bs[kc * GBS + nc0 + nt * 8]);
                bfr[nt][1] = f2tf(Bs[(kc + 4) * GBS + nc0 + nt * 8]);
            }
#pragma unroll
            for (int mt = 0; mt < 4; mt++)
#pragma unroll
                for (int nt = 0; nt < 4; nt++)
                    mma8(acc[mt][nt], a[mt], bfr[nt]);
        }
        __syncthreads();
        if (it + 2 < iters) {
            float* As2 = gsm + (it & 1) * GSTG;
            gemm_issue(A, B, As2, As2 + 128 * GAS, bRow, bCol, (it + 2) * 32, K, N, tid);
        } else {
            CPA_COMMIT();
        }
    }
    const int r0 = bRow + wr + (lane >> 2);
    const int c0 = bCol + wc + 2 * (lane & 3);
#pragma unroll
    for (int mt = 0; mt < 4; mt++)
#pragma unroll
        for (int nt = 0; nt < 4; nt++) {
            float* p1 = C + (size_t)(r0 + mt * 16) * N + c0 + nt * 8;
            float* p2 = C + (size_t)(r0 + mt * 16 + 8) * N + c0 + nt * 8;
            *(float2*)p1 = make_float2(acc[mt][nt][0], acc[mt][nt][1]);
            *(float2*)p2 = make_float2(acc[mt][nt][2], acc[mt][nt][3]);
        }
}

// ---------------- activations (unchanged) -----------------------------------
__global__ void __launch_bounds__(256) act_kernel()
{
    int wg = (blockIdx.x * 256 + threadIdx.x) >> 5;
    int lane = threadIdx.x & 31;
    if (wg < 32768) {
        float4 x = *(const float4*)(g_q + (size_t)wg * 128 + lane * 4);
        float m = fmaxf(fmaxf(x.x, x.y), fmaxf(x.z, x.w));
#pragma unroll
        for (int o = 16; o; o >>= 1) m = fmaxf(m, __shfl_xor_sync(~0u, m, o));
        float e0 = __expf(x.x - m), e1 = __expf(x.y - m), e2 = __expf(x.z - m), e3 = __expf(x.w - m);
        float s = e0 + e1 + e2 + e3;
#pragma unroll
        for (int o = 16; o; o >>= 1) s += __shfl_xor_sync(~0u, s, o);
        float inv = 1.f / s;
        *(float4*)(g_ql + (size_t)wg * 128 + lane * 4) = make_float4(e0 * inv, e1 * inv, e2 * inv, e3 * inv);
    } else {
        int rk = wg - 32768;
        if (rk >= 8192) return;
        float4 x = *(const float4*)(g_k + (size_t)rk * 128 + lane * 4);
        float m = fmaxf(fmaxf(x.x, x.y), fmaxf(x.z, x.w));
#pragma unroll
        for (int o = 16; o; o >>= 1) m = fmaxf(m, __shfl_xor_sync(~0u, m, o));
        float e0 = __expf(x.x - m), e1 = __expf(x.y - m), e2 = __expf(x.z - m), e3 = __expf(x.w - m);
        float s = e0 + e1 + e2 + e3;
#pragma unroll
        for (int o = 16; o; o >>= 1) s += __shfl_xor_sync(~0u, s, o);
        float inv = 1.f / s;
        *(float4*)(g_kl + (size_t)rk * 128 + lane * 4) = make_float4(e0 * inv, e1 * inv, e2 * inv, e3 * inv);
        float4 bt;
        bt.x = (fminf(x.x, 0.f) - log1pf(__expf(-fabsf(x.x)))) * 0.0625f;
        bt.y = (fminf(x.y, 0.f) - log1pf(__expf(-fabsf(x.y)))) * 0.0625f;
        bt.z = (fminf(x.z, 0.f) - log1pf(__expf(-fabsf(x.z)))) * 0.0625f;
        bt.w = (fminf(x.w, 0.f) - log1pf(__expf(-fabsf(x.w)))) * 0.0625f;
        *(float4*)(g_bt + (size_t)rk * 128 + lane * 4) = bt;
    }
}

// ---------------- pairwise-dot (unchanged) ----------------------------------
__global__ void __launch_bounds__(256) pairdot_kernel(int isP)
{
    extern __shared__ float sm[];
    float* Xs = sm;
    float* Ys = sm + 8192;
    const int blk = blockIdx.x;
    const int tid = threadIdx.x;
    const float* xbase; const float* ybase; float* out; int ldx, ldy;
    if (isP) {
        int b = blk >> 8, h = (blk >> 4) & 15, cn = blk & 15;
        int tok0 = b * 1024 + cn * 64;
        xbase = g_ql + (size_t)tok0 * HIDN + h * 128; ldx = HIDN;
        ybase = g_kl + (size_t)tok0 * KVD + (h >> 2) * 128; ldy = KVD;
        out = g_P + (size_t)blk * 4096;
    } else {
        int b = blk >> 6, kv = (blk >> 4) & 3, cn = blk & 15;
        int tok0 = b * 1024 + cn * 64;
        xbase = g_kl + (size_t)tok0 * KVD + kv * 128; ldx = KVD;
        ybase = xbase; ldy = KVD;
        out = g_A + (size_t)blk * 4096;
    }
    for (int i = tid * 4; i < 8192; i += 1024) {
        int r = i >> 7, c = i & 127;
        *(float4*)(Xs + i) = *(const float4*)(xbase + (size_t)r * ldx + c);
        *(float4*)(Ys + i) = *(const float4*)(ybase + (size_t)r * ldy + c);
    }
    __syncthreads();
    const int a0 = (tid >> 4) * 4, b0 = (tid & 15) * 4;
    float s4[4][4];
#pragma unroll
    for (int i = 0; i < 4; i++)
#pragma unroll
        for (int j = 0; j < 4; j++) s4[i][j] = 0.f;
    for (int d = 0; d < 128; d += 4) {
        float4 qa[4], kb[4];
#pragma unroll
        for (int i = 0; i < 4; i++) qa[i] = *(const float4*)(Xs + (a0 + i) * 128 + d);
#pragma unroll
        for (int j = 0; j < 4; j++) kb[j] = *(const float4*)(Ys + (b0 + j) * 128 + d);
#pragma unroll
        for (int i = 0; i < 4; i++)
#pragma unroll
            for (int j = 0; j < 4; j++)
                s4[i][j] += qa[i].x * kb[j].x + qa[i].y * kb[j].y + qa[i].z * kb[j].z + qa[i].w * kb[j].w;
    }
#pragma unroll
    for (int i = 0; i < 4; i++)
#pragma unroll
        for (int j = 0; j < 4; j++) {
            int t = a0 + i, s = b0 + j;
            bool keep = isP ? (s <= t) : (s < t);
            out[t * 64 + s] = keep ? s4[i][j] : 0.f;
        }
}

// ---------------- M inverse precompute: plain M (diag = 1 exact) -------------
__global__ void __launch_bounds__(128) minv_kernel()
{
    extern __shared__ float ms[];
    float* As = ms;
    float* Xs = ms + 4096;
    float* bs = Xs + 8320;
    const int tid = threadIdx.x;
    const int c0 = blockIdx.x * 2, ach = blockIdx.y;
    const int b = ach >> 6, kv = (ach >> 4) & 3, cn = ach & 15;
    const int tok0 = b * 1024 + cn * 64;

    for (int i = tid * 4; i < 4096; i += 512)
        *(float4*)(As + i) = *(const float4*)(g_A + (size_t)ach * 4096 + i);
    {
        int c = tid >> 6, t = tid & 63;
        bs[c * 64 + t] = g_bt[(size_t)(tok0 + t) * KVD + kv * 128 + c0 + c];
    }
    __syncthreads();

    const int c = tid >> 6, s = tid & 63;
    float* Xc = Xs + c * 4160;
    Xc[s * 65 + s] = 1.f;
    for (int i = s + 1; i < 64; i++) {
        float acc = 0.f;
        for (int p = s; p < i; p++) acc += As[i * 64 + p] * Xc[p * 65 + s];
        Xc[i * 65 + s] = -bs[c * 64 + i] * acc;
    }
    __nv_bfloat16* dst = g_M + (size_t)((ach * 128 + c0 + c) * 64) * 64 + s;
    for (int t = 0; t < 64; t++) {
        float val = (t > s) ? Xc[t * 65 + s] : (t == s ? 1.f : 0.f);
        dst[t * 64] = __float2bfloat16(val);
    }
}

// ---------------- flash attention (unchanged) ---------------------------------
#define FQS 132
#define FKS 132
#define FVS 136
#define FSS 68

__global__ void __launch_bounds__(256) flash_kernel(
    const float* __restrict__ q, const float* __restrict__ k,
    const float* __restrict__ v, float* __restrict__ comb)
{
    extern __shared__ float fsm[];
    float* Qs = fsm;
    float* Ks = Qs + 64 * FQS;
    float* Vs = Ks + 64 * FKS;
    float* Ss = Vs + 64 * FVS;
    float* msh = Ss + 64 * FSS;
    float* lsh = msh + 64;
    float* csh = lsh + 64;
    const int tid = threadIdx.x, lane = tid & 31, warp = tid >> 5;
    const int qt = 15 - (blockIdx.x & 15);
    const int bh = blockIdx.y;
    const int b = bh >> 4, h = bh & 15, kvh = h >> 2;
    const float scale = 0.08838834764831845f;
    {
        const float* qb = q + (size_t)(b * 1024 + qt * 64) * HIDN + h * 128;
        for (int i = tid; i < 2048; i += 256) {
            int r = i >> 5, c4 = (i & 31) * 4;
            float4 t4 = *(const float4*)(qb + (size_t)r * HIDN + c4);
            Qs[r * FQS + c4 + 0] = f2tf_f(t4.x * scale);
            Qs[r * FQS + c4 + 1] = f2tf_f(t4.y * scale);
            Qs[r * FQS + c4 + 2] = f2tf_f(t4.z * scale);
            Qs[r * FQS + c4 + 3] = f2tf_f(t4.w * scale);
        }
    }
    if (tid < 64) { msh[tid] = -1e30f; lsh[tid] = 0.f; }
    const int wr2 = (warp >> 2) * 32, wc2 = (warp & 3) * 32;
    float oc[2][4][4];
#pragma unroll
    for (int mt = 0; mt < 2; mt++)
#pragma unroll
        for (int nt = 0; nt < 4; nt++)
#pragma unroll
            for (int i = 0; i < 4; i++) oc[mt][nt][i] = 0.f;

    for (int j = 0; j <= qt; j++) {
        __syncthreads();
        {
            const float* kb = k + (size_t)(b * 1024 + j * 64) * KVD + kvh * 128;
            const float* vb = v + (size_t)(b * 1024 + j * 64) * KVD + kvh * 128;
            for (int i = tid; i < 2048; i += 256) {
                int r = i >> 5, c4 = (i & 31) * 4;
                float4 k4 = *(const float4*)(kb + (size_t)r * KVD + c4);
                Ks[r * FKS + c4 + 0] = f2tf_f(k4.x); Ks[r * FKS + c4 + 1] = f2tf_f(k4.y);
                Ks[r * FKS + c4 + 2] = f2tf_f(k4.z); Ks[r * FKS + c4 + 3] = f2tf_f(k4.w);
                float4 v4 = *(const float4*)(vb + (size_t)r * KVD + c4);
                Vs[r * FVS + c4 + 0] = f2tf_f(v4.x); Vs[r * FVS + c4 + 1] = f2tf_f(v4.y);
                Vs[r * FVS + c4 + 2] = f2tf_f(v4.z); Vs[r * FVS + c4 + 3] = f2tf_f(v4.w);
            }
        }
        __syncthreads();
        {
            float sc[2][2][4];
#pragma unroll
            for (int mt = 0; mt < 2; mt++)
#pragma unroll
                for (int nt = 0; nt < 2; nt++)
#pragma unroll
                    for (int i = 0; i < 4; i++) sc[mt][nt][i] = 0.f;
            const int swr = (warp >> 2) * 32, swc = (warp & 3) * 16;
            const int r0 = swr + (lane >> 2);
#pragma unroll
            for (int ks = 0; ks < 16; ks++) {
                const int kc = ks * 8 + (lane & 3);
                unsigned a[2][4], bf[2][2];
#pragma unroll
                for (int mt = 0; mt < 2; mt++) {
                    a[mt][0] = __float_as_uint(Qs[(r0 + mt * 16) * FQS + kc]);
                    a[mt][1] = __float_as_uint(Qs[(r0 + mt * 16 + 8) * FQS + kc]);
                    a[mt][2] = __float_as_uint(Qs[(r0 + mt * 16) * FQS + kc + 4]);
                    a[mt][3] = __float_as_uint(Qs[(r0 + mt * 16 + 8) * FQS + kc + 4]);
                }
                const int nc = swc + (lane >> 2);
#pragma unroll
                for (int nt = 0; nt < 2; nt++) {
                    bf[nt][0] = __float_as_uint(Ks[(nc + nt * 8) * FKS + kc]);
                    bf[nt][1] = __float_as_uint(Ks[(nc + nt * 8) * FKS + kc + 4]);
                }
#pragma unroll
                for (int mt = 0; mt < 2; mt++)
#pragma unroll
                    for (int nt = 0; nt < 2; nt++)
                        mma8(sc[mt][nt], a[mt], bf[nt]);
            }
#pragma unroll
            for (int mt = 0; mt < 2; mt++)
#pragma unroll
                for (int nt = 0; nt < 2; nt++) {
                    int rr = swr + mt * 16 + (lane >> 2);
                    int cc = swc + nt * 8 + 2 * (lane & 3);
                    Ss[rr * FSS + cc] = sc[mt][nt][0];
                    Ss[rr * FSS + cc + 1] = sc[mt][nt][1];
                    Ss[(rr + 8) * FSS + cc] = sc[mt][nt][2];
                    Ss[(rr + 8) * FSS + cc + 1] = sc[mt][nt][3];
                }
        }
        __syncthreads();
        {
            const int row = tid >> 2, sub = tid & 3;
            float* srow = Ss + row * FSS + sub * 16;
            float pv[16];
            float mx = -1e30f;
#pragma unroll
            for (int ii = 0; ii < 16; ii++) {
                float x = srow[ii];
                if (j == qt && (sub * 16 + ii) > row) x = -1e30f;
                pv[ii] = x;
                mx = fmaxf(mx, x);
            }
            mx = fmaxf(mx, __shfl_xor_sync(~0u, mx, 1));
            mx = fmaxf(mx, __shfl_xor_sync(~0u, mx, 2));
            float mold = msh[row];
            float mnew = fmaxf(mx, mold);
            float cf = __expf(mold - mnew);
            float lsum = 0.f;
#pragma unroll
            for (int ii = 0; ii < 16; ii++) {
                float p = __expf(pv[ii] - mnew);
                srow[ii] = f2tf_f(p);
                lsum += p;
            }
            lsum += __shfl_xor_sync(~0u, lsum, 1);
            lsum += __shfl_xor_sync(~0u, lsum, 2);
            if (sub == 0) {
                msh[row] = mnew;
                lsh[row] = lsh[row] * cf + lsum;
                csh[row] = cf;
            }
        }
        __syncthreads();
        {
            const int rA = wr2 + (lane >> 2);
#pragma unroll
            for (int mt = 0; mt < 2; mt++) {
                float cl = csh[rA + mt * 16];
                float ch = csh[rA + mt * 16 + 8];
#pragma unroll
                for (int nt = 0; nt < 4; nt++) {
                    oc[mt][nt][0] *= cl; oc[mt][nt][1] *= cl;
                    oc[mt][nt][2] *= ch; oc[mt][nt][3] *= ch;
                }
            }
#pragma unroll
            for (int ks = 0; ks < 8; ks++) {
                const int kc = ks * 8 + (lane & 3);
                unsigned a[2][4], bf[4][2];
#pragma unroll
                for (int mt = 0; mt < 2; mt++) {
                    a[mt][0] = __float_as_uint(Ss[(rA + mt * 16) * FSS + kc]);
                    a[mt][1] = __float_as_uint(Ss[(rA + mt * 16 + 8) * FSS + kc]);
                    a[mt][2] = __float_as_uint(Ss[(rA + mt * 16) * FSS + kc + 4]);
                    a[mt][3] = __float_as_uint(Ss[(rA + mt * 16 + 8) * FSS + kc + 4]);
                }
                const int nc = wc2 + (lane >> 2);
#pragma unroll
                for (int nt = 0; nt < 4; nt++) {
                    bf[nt][0] = __float_as_uint(Vs[kc * FVS + nc + nt * 8]);
                    bf[nt][1] = __float_as_uint(Vs[(kc + 4) * FVS + nc + nt * 8]);
                }
#pragma unroll
                for (int mt = 0; mt < 2; mt++)
#pragma unroll
                    for (int nt = 0; nt < 4; nt++)
                        mma8(oc[mt][nt], a[mt], bf[nt]);
            }
        }
    }
#pragma unroll
    for (int mt = 0; mt < 2; mt++) {
        int r1 = wr2 + mt * 16 + (lane >> 2);
        int r2 = r1 + 8;
        float il1 = 0.5f / lsh[r1];
        float il2 = 0.5f / lsh[r2];
        size_t base1 = (size_t)(b * 1024 + qt * 64 + r1) * HIDN + h * 128;
        size_t base2 = (size_t)(b * 1024 + qt * 64 + r2) * HIDN + h * 128;
#pragma unroll
        for (int nt = 0; nt < 4; nt++) {
            int col = wc2 + nt * 8 + 2 * (lane & 3);
            *(float2*)(comb + base1 + col) = make_float2(oc[mt][nt][0] * il1, oc[mt][nt][1] * il1);
            *(float2*)(comb + base2 + col) = make_float2(oc[mt][nt][2] * il2, oc[mt][nt][3] * il2);
        }
    }
}

// ---------------- delta-rule: 128 blocks x 256 threads, 1 channel ------------
// stage floats: K 64*132=8448 | M bf16 64x72 = 2304 fl | v 64 | b 64 => 10880
#define DSTG7 10880

__device__ __forceinline__ void delta_prefetch7(float* base, int gn, int c0, int tid)
{
    int bb = gn >> 8, hh = (gn >> 4) & 15, cn = gn & 15, kv = hh >> 2;
    int tok0 = bb * 1024 + cn * 64;
    int ach = (bb * 4 + kv) * 16 + cn;
    float* K_ = base;
    __nv_bfloat16* Mb = (__nv_bfloat16*)(base + 8448);
    float* v_ = base + 10752;
    float* b_ = base + 10816;
#pragma unroll
    for (int i = 0; i < 8; i++) {
        int jj = tid + 256 * i; int tr = jj >> 5, cc = (jj & 31) << 2;
        cpa16(K_ + tr * 132 + cc, g_kl + (size_t)(tok0 + tr) * KVD + kv * 128 + cc);
    }
#pragma unroll
    for (int i = 0; i < 2; i++) {
        int jj = tid + 256 * i; int row = jj >> 3, k8 = (jj & 7) * 8;
        cpa16(Mb + row * 72 + k8,
              g_M + ((size_t)(ach * 128 + c0) * 64 + row) * 64 + k8);
    }
    if (tid < 64)
        cpa4(v_ + tid, g_v + (size_t)(tok0 + tid) * KVD + kv * 128 + c0);
    else if (tid < 128) {
        int tt = tid - 64;
        cpa4(b_ + tt, g_bt + (size_t)(tok0 + tt) * KVD + kv * 128 + c0);
    }
}

__global__ void __launch_bounds__(256) delta_kernel()
{
    extern __shared__ float dsm[];
    float* Ssh = dsm + 2 * DSTG7;   // 128
    float* r_ = Ssh + 128;          // 68
    float* u_ = r_ + 68;            // 68
    const int tid = threadIdx.x;
    const int c0 = blockIdx.x;              // one channel
    const int qt = tid >> 2, qh = tid & 3;  // phase B / matvec mapping
    const int de = tid >> 1, th = tid & 1;  // phase E mapping

    if (tid < 128) Ssh[tid] = 0.f;
    delta_prefetch7(dsm, 0, c0, tid);
    CPA_COMMIT();
    __syncthreads();

    for (int gc = 0; gc < NGC; gc++) {
        if (gc + 1 < NGC) delta_prefetch7(dsm + ((gc + 1) & 1) * DSTG7, gc + 1, c0, tid);
        CPA_COMMIT();
        CPA_WAIT1();
        __syncthreads();

        float* base = dsm + (gc & 1) * DSTG7;
        float* K_ = base;
        const __nv_bfloat16* Mb = (const __nv_bfloat16*)(base + 8448);
        float* v_ = base + 10752;
        float* b_ = base + 10816;

        // S0 snapshot [gc][k][c0]
        if (tid < 128)
            g_S0T[((size_t)gc * 128 + tid) * 128 + c0] = Ssh[tid];

        // phase B: token qt, quarter qh; mm = k_qt . S ; r = beta*(v - mm)
        {
            float mm = 0.f;
            const float* krow = K_ + qt * 132 + qh * 32;
            const float* scol = Ssh + qh * 32;
#pragma unroll
            for (int d = 0; d < 32; d += 4) {
                float4 k4 = *(const float4*)(krow + d);
                float4 s4 = *(const float4*)(scol + d);
                mm += k4.x * s4.x + k4.y * s4.y + k4.z * s4.z + k4.w * s4.w;
            }
            mm += __shfl_xor_sync(~0u, mm, 1);
            mm += __shfl_xor_sync(~0u, mm, 2);
            if (qh == 0) r_[qt] = b_[qt] * (v_[qt] - mm);
        }
        __syncthreads();

        // u = M r : quarter-row each, 2 shfl combine (beta already in r, fp32)
        {
            float u = 0.f;
            const __nv_bfloat16* mrow = Mb + qt * 72 + qh * 16;
            const float* rr = r_ + qh * 16;
#pragma unroll
            for (int j = 0; j < 2; j++) {
                uint4 w = *(const uint4*)(mrow + j * 8);
                float2 f0 = __bfloat1622float2(*(__nv_bfloat162*)&w.x);
                float2 f1 = __bfloat1622float2(*(__nv_bfloat162*)&w.y);
                float2 f2 = __bfloat1622float2(*(__nv_bfloat162*)&w.z);
                float2 f3 = __bfloat1622float2(*(__nv_bfloat162*)&w.w);
                float4 ra = *(const float4*)(rr + j * 8);
                float4 rb = *(const float4*)(rr + j * 8 + 4);
                u += f0.x * ra.x + f0.y * ra.y + f1.x * ra.z + f1.y * ra.w
                   + f2.x * rb.x + f2.y * rb.y + f3.x * rb.z + f3.y * rb.w;
            }
            u += __shfl_xor_sync(~0u, u, 1);
            u += __shfl_xor_sync(~0u, u, 2);
            if (qh == 0) {
                u_[qt] = u;
                g_U[((size_t)gc * 64 + qt) * 128 + c0] = u;
            }
        }
        __syncthreads();

        // phase E: S[de] += sum_t2 K[t2][de] * u[t2], split t2 over th
        {
            float s = 0.f;
            const int t0 = th * 32;
#pragma unroll 8
            for (int t2 = 0; t2 < 32; t2++)
                s += K_[(t0 + t2) * 132 + de] * u_[t0 + t2];
            s += __shfl_xor_sync(~0u, s, 1);
            if (th == 0) Ssh[de] += s;
        }
        __syncthreads();
    }
}

// ---------------- okernel (unchanged) ----------------------------------------
__global__ void __launch_bounds__(256) okernel(float* __restrict__ comb)
{
    extern __shared__ float osm[];
    float* Qs = osm;               // 64*132
    float* Ps = Qs + 8448;         // 64*68
    float* Us = Ps + 4352;         // 64*132
    float* S0p = Us + 8448;        // 32*132
    const int gc = blockIdx.x;
    const int b = gc >> 8, h = (gc >> 4) & 15, cn = gc & 15;
    const int tok0 = b * 1024 + cn * 64;
    const int tid = threadIdx.x;

    for (int i = tid; i < 2048; i += 256) {
        int r = i >> 5, c4 = (i & 31) * 4;
        *(float4*)(Qs + r * 132 + c4) =
            *(const float4*)(g_ql + (size_t)(tok0 + r) * HIDN + h * 128 + c4);
    }
    for (int i = tid; i < 1024; i += 256) {
        int r = i >> 4, c4 = (i & 15) * 4;
        *(float4*)(Ps + r * 68 + c4) = *(const float4*)(g_P + (size_t)gc * 4096 + i * 4);
    }
    for (int i = tid; i < 2048; i += 256) {
        int s = i >> 5, c4 = (i & 31) * 4;
        *(float4*)(Us + s * 132 + c4) = *(const float4*)(g_U + ((size_t)gc * 64 + s) * 128 + c4);
    }
    __syncthreads();

    const int t0 = (tid >> 4) * 4, cc0 = (tid & 15) * 8;
    float acc[4][8];
#pragma unroll
    for (int i = 0; i < 4; i++)
#pragma unroll
        for (int j = 0; j < 8; j++) acc[i][j] = 0.f;
    for (int s = 0; s < 64; s++) {
        float4 ua = *(const float4*)(Us + s * 132 + cc0);
        float4 ub = *(const float4*)(Us + s * 132 + cc0 + 4);
#pragma unroll
        for (int i = 0; i < 4; i++) {
            float p = Ps[(t0 + i) * 68 + s];
            acc[i][0] += p * ua.x; acc[i][1] += p * ua.y;
            acc[i][2] += p * ua.z; acc[i][3] += p * ua.w;
            acc[i][4] += p * ub.x; acc[i][5] += p * ub.y;
            acc[i][6] += p * ub.z; acc[i][7] += p * ub.w;
        }
    }
    for (int kp = 0; kp < 128; kp += 32) {
        __syncthreads();
        for (int i = tid; i < 1024; i += 256) {
            int k = i >> 5, c4 = (i & 31) * 4;
            *(float4*)(S0p + k * 132 + c4) =
                *(const float4*)(g_S0T + ((size_t)gc * 128 + kp + k) * 128 + c4);
        }
        __syncthreads();
        for (int k = 0; k < 32; k++) {
            float4 sa = *(const float4*)(S0p + k * 132 + cc0);
            float4 sb = *(const float4*)(S0p + k * 132 + cc0 + 4);
#pragma unroll
            for (int i = 0; i < 4; i++) {
                float qv = Qs[(t0 + i) * 132 + kp + k];
                acc[i][0] += qv * sa.x; acc[i][1] += qv * sa.y;
                acc[i][2] += qv * sa.z; acc[i][3] += qv * sa.w;
                acc[i][4] += qv * sb.x; acc[i][5] += qv * sb.y;
                acc[i][6] += qv * sb.z; acc[i][7] += qv * sb.w;
            }
        }
    }
#pragma unroll
    for (int i = 0; i < 4; i++) {
        float* dst = comb + (size_t)(tok0 + t0 + i) * HIDN + h * 128 + cc0;
        float4 o1 = *(float4*)dst;
        float4 o2 = *(float4*)(dst + 4);
        o1.x += 0.5f * acc[i][0]; o1.y += 0.5f * acc[i][1];
        o1.z += 0.5f * acc[i][2]; o1.w += 0.5f * acc[i][3];
        o2.x += 0.5f * acc[i][4]; o2.y += 0.5f * acc[i][5];
        o2.z += 0.5f * acc[i][6]; o2.w += 0.5f * acc[i][7];
        *(float4*)dst = o1; *(float4*)(dst + 4) = o2;
    }
}

// ---------------- launch -----------------------------------------------------
extern "C" void kernel_launch(void* const* d_in, const int* in_sizes, int n_in,
                              void* d_out, int out_size)
{
    const float* hs = (const float*)d_in[0];
    const float* Wq = (const float*)d_in[1];
    const float* Wk = (const float*)d_in[2];
    const float* Wv = (const float*)d_in[3];
    const float* Wo = (const float*)d_in[4];
    float* out = (float*)d_out;

    float *p_q, *p_k, *p_v, *p_comb;
    cudaGetSymbolAddress((void**)&p_q, g_q);
    cudaGetSymbolAddress((void**)&p_k, g_k);
    cudaGetSymbolAddress((void**)&p_v, g_v);
    cudaGetSymbolAddress((void**)&p_comb, g_comb);

    const int gemm_smem = 2 * GSTG * 4;
    const int pair_smem = 8192 * 2 * 4;
    const int flash_smem = (64 * FQS + 64 * FKS + 64 * FVS + 64 * FSS + 192) * 4;
    const int delta_smem = (2 * DSTG7 + 128 + 68 + 68) * 4;
    const int minv_smem = (4096 + 8320 + 128) * 4;
    const int o_smem = (8448 + 4352 + 8448 + 32 * 132) * 4;
    cudaFuncSetAttribute(mma_gemm, cudaFuncAttributeMaxDynamicSharedMemorySize, gemm_smem);
    cudaFuncSetAttribute(pairdot_kernel, cudaFuncAttributeMaxDynamicSharedMemorySize, pair_smem);
    cudaFuncSetAttribute(flash_kernel, cudaFuncAttributeMaxDynamicSharedMemorySize, flash_smem);
    cudaFuncSetAttribute(delta_kernel, cudaFuncAttributeMaxDynamicSharedMemorySize, delta_smem);
    cudaFuncSetAttribute(minv_kernel, cudaFuncAttributeMaxDynamicSharedMemorySize, minv_smem);
    cudaFuncSetAttribute(okernel, cudaFuncAttributeMaxDynamicSharedMemorySize, o_smem);

    mma_gemm<<<dim3(16, 16), 256, gemm_smem>>>(hs, Wq, p_q, TOK, HIDN, HIDN);
    mma_gemm<<<dim3(4, 16), 256, gemm_smem>>>(hs, Wk, p_k, TOK, KVD, HIDN);
    mma_gemm<<<dim3(4, 16), 256, gemm_smem>>>(hs, Wv, p_v, TOK, KVD, HIDN);
    act_kernel<<<5120, 256>>>();
    pairdot_kernel<<<NACH, 256, pair_smem>>>(0);
    minv_kernel<<<dim3(64, 128), 128, minv_smem>>>();
    pairdot_kernel<<<NGC, 256, pair_smem>>>(1);
    flash_kernel<<<dim3(16, 32), 256, flash_smem>>>(p_q, p_k, p_v, p_comb);
    delta_kernel<<<128, 256, delta_smem>>>();
    okernel<<<NGC, 256, o_smem>>>(p_comb);
    mma_gemm<<<dim3(16, 16), 256, gemm_smem>>>(p_comb, Wo, out, TOK, HIDN, HIDN);
}

// round 13
// speedup vs baseline: 1.2205x; 1.2205x over previous
#include <cuda_runtime.h>
#include <cuda_bf16.h>
#include <math.h>

#define TOK 2048
#define HIDN 2048
#define KVD 512
#define CHK 64
#define NGC 512
#define NACH 128

__device__ float g_q[TOK * HIDN];
__device__ float g_k[TOK * KVD];
__device__ float g_v[TOK * KVD];
__device__ float g_ql[TOK * HIDN];
__device__ float g_kl[TOK * KVD];
__device__ float g_bt[TOK * KVD];
__device__ float g_A[NACH * CHK * CHK];
__device__ float g_P[NGC * CHK * CHK];
__device__ float g_comb[TOK * HIDN];
__device__ __nv_bfloat16 g_M[(size_t)NACH * 128 * CHK * CHK];
__device__ float g_S0T[(size_t)NGC * 128 * 128];   // [gc][k][c]
__device__ float g_U[(size_t)NGC * CHK * 128];     // [gc][t][c]
// pre-rounded (tf32) copies of GEMM operands
__device__ float g_hsr[TOK * HIDN];
__device__ float g_wqr[HIDN * HIDN];
__device__ float g_wkr[HIDN * KVD];
__device__ float g_wvr[HIDN * KVD];
__device__ float g_wor[HIDN * HIDN];

__device__ __forceinline__ unsigned f2tf(float x) {
    unsigned u; asm("cvt.rna.tf32.f32 %0, %1;" : "=r"(u) : "f"(x)); return u;
}
__device__ __forceinline__ float f2tf_f(float x) { return __uint_as_float(f2tf(x)); }

__device__ __forceinline__ void mma8(float c[4], const unsigned a[4], const unsigned b[2]) {
    asm volatile(
        "mma.sync.aligned.m16n8k8.row.col.f32.tf32.tf32.f32 "
        "{%0,%1,%2,%3}, {%4,%5,%6,%7}, {%8,%9}, {%0,%1,%2,%3};"
        : "+f"(c[0]), "+f"(c[1]), "+f"(c[2]), "+f"(c[3])
        : "r"(a[0]), "r"(a[1]), "r"(a[2]), "r"(a[3]), "r"(b[0]), "r"(b[1]));
}
__device__ __forceinline__ void cpa16(void* dst, const void* src) {
    unsigned d = (unsigned)__cvta_generic_to_shared(dst);
    asm volatile("cp.async.ca.shared.global [%0], [%1], 16;" :: "r"(d), "l"(src) : "memory");
}
__device__ __forceinline__ void cpa4(void* dst, const void* src) {
    unsigned d = (unsigned)__cvta_generic_to_shared(dst);
    asm volatile("cp.async.ca.shared.global [%0], [%1], 4;" :: "r"(d), "l"(src) : "memory");
}
#define CPA_COMMIT() asm volatile("cp.async.commit_group;" ::: "memory")
#define CPA_WAIT1()  asm volatile("cp.async.wait_group 1;" ::: "memory")

// ---------------- rounding pre-pass ------------------------------------------
__global__ void __launch_bounds__(256) round_kernel(
    const float* __restrict__ src, float* __restrict__ dst, int n4)
{
    int i = blockIdx.x * 256 + threadIdx.x;
    if (i < n4) {
        float4 x = ((const float4*)src)[i];
        x.x = f2tf_f(x.x); x.y = f2tf_f(x.y);
        x.z = f2tf_f(x.z); x.w = f2tf_f(x.w);
        ((float4*)dst)[i] = x;
    }
}

// ------------------------ tf32 MMA GEMM (inputs pre-rounded) -----------------
#define GAS 36
#define GBS 136
#define GSTG (128 * GAS + 32 * GBS)

__device__ __forceinline__ void gemm_issue(
    const float* __restrict__ A, const float* __restrict__ B,
    float* As, float* Bs, int bRow, int bCol, int k0, int K, int N, int tid)
{
#pragma unroll
    for (int i = 0; i < 4; i++) {
        int lin = tid + 256 * i;
        int r = lin >> 3, c4 = (lin & 7) << 2;
        cpa16(As + r * GAS + c4, A + (size_t)(bRow + r) * K + k0 + c4);
    }
#pragma unroll
    for (int i = 0; i < 4; i++) {
        int lin = tid + 256 * i;
        int r = lin >> 5, c4 = (lin & 31) << 2;
        cpa16(Bs + r * GBS + c4, B + (size_t)(k0 + r) * N + bCol + c4);
    }
    CPA_COMMIT();
}

__global__ void __launch_bounds__(256) mma_gemm(
    const float* __restrict__ A, const float* __restrict__ B,
    float* __restrict__ C, int M, int N, int K)
{
    extern __shared__ float gsm[];
    const int tid = threadIdx.x, lane = tid & 31, warp = tid >> 5;
    const int bRow = blockIdx.y * 128, bCol = blockIdx.x * 128;
    const int wr = (warp >> 2) * 64, wc = (warp & 3) * 32;
    float acc[4][4][4];
#pragma unroll
    for (int mt = 0; mt < 4; mt++)
#pragma unroll
        for (int nt = 0; nt < 4; nt++)
#pragma unroll
            for (int i = 0; i < 4; i++) acc[mt][nt][i] = 0.f;

    gemm_issue(A, B, gsm, gsm + 128 * GAS, bRow, bCol, 0, K, N, tid);
    gemm_issue(A, B, gsm + GSTG, gsm + GSTG + 128 * GAS, bRow, bCol, 32, K, N, tid);

    const int iters = K / 32;
    for (int it = 0; it < iters; it++) {
        CPA_WAIT1();
        __syncthreads();
        float* As = gsm + (it & 1) * GSTG;
        float* Bs = As + 128 * GAS;
#pragma unroll
        for (int kk = 0; kk < 4; kk++) {
            unsigned a[4][4], bfr[4][2];
            const int kc = kk * 8 + (lane & 3);
            const int r0 = wr + (lane >> 2);
#pragma unroll
            for (int mt = 0; mt < 4; mt++) {
                a[mt][0] = __float_as_uint(As[(r0 + mt * 16) * GAS + kc]);
                a[mt][1] = __float_as_uint(As[(r0 + mt * 16 + 8) * GAS + kc]);
                a[mt][2] = __float_as_uint(As[(r0 + mt * 16) * GAS + kc + 4]);
                a[mt][3] = __float_as_uint(As[(r0 + mt * 16 + 8) * GAS + kc + 4]);
            }
            const int nc0 = wc + (lane >> 2);
#pragma unroll
            for (int nt = 0; nt < 4; nt++) {
                bfr[nt][0] = __float_as_uint(Bs[kc * GBS + nc0 + nt * 8]);
                bfr[nt][1] = __float_as_uint(Bs[(kc + 4) * GBS + nc0 + nt * 8]);
            }
#pragma unroll
            for (int mt = 0; mt < 4; mt++)
#pragma unroll
                for (int nt = 0; nt < 4; nt++)
                    mma8(acc[mt][nt], a[mt], bfr[nt]);
        }
        __syncthreads();
        if (it + 2 < iters) {
            float* As2 = gsm + (it & 1) * GSTG;
            gemm_issue(A, B, As2, As2 + 128 * GAS, bRow, bCol, (it + 2) * 32, K, N, tid);
        } else {
            CPA_COMMIT();
        }
    }
    const int r0 = bRow + wr + (lane >> 2);
    const int c0 = bCol + wc + 2 * (lane & 3);
#pragma unroll
    for (int mt = 0; mt < 4; mt++)
#pragma unroll
        for (int nt = 0; nt < 4; nt++) {
            float* p1 = C + (size_t)(r0 + mt * 16) * N + c0 + nt * 8;
            float* p2 = C + (size_t)(r0 + mt * 16 + 8) * N + c0 + nt * 8;
            *(float2*)p1 = make_float2(acc[mt][nt][0], acc[mt][nt][1]);
            *(float2*)p2 = make_float2(acc[mt][nt][2], acc[mt][nt][3]);
        }
}

// ---------------- activations (unchanged) -----------------------------------
__global__ void __launch_bounds__(256) act_kernel()
{
    int wg = (blockIdx.x * 256 + threadIdx.x) >> 5;
    int lane = threadIdx.x & 31;
    if (wg < 32768) {
        float4 x = *(const float4*)(g_q + (size_t)wg * 128 + lane * 4);
        float m = fmaxf(fmaxf(x.x, x.y), fmaxf(x.z, x.w));
#pragma unroll
        for (int o = 16; o; o >>= 1) m = fmaxf(m, __shfl_xor_sync(~0u, m, o));
        float e0 = __expf(x.x - m), e1 = __expf(x.y - m), e2 = __expf(x.z - m), e3 = __expf(x.w - m);
        float s = e0 + e1 + e2 + e3;
#pragma unroll
        for (int o = 16; o; o >>= 1) s += __shfl_xor_sync(~0u, s, o);
        float inv = 1.f / s;
        *(float4*)(g_ql + (size_t)wg * 128 + lane * 4) = make_float4(e0 * inv, e1 * inv, e2 * inv, e3 * inv);
    } else {
        int rk = wg - 32768;
        if (rk >= 8192) return;
        float4 x = *(const float4*)(g_k + (size_t)rk * 128 + lane * 4);
        float m = fmaxf(fmaxf(x.x, x.y), fmaxf(x.z, x.w));
#pragma unroll
        for (int o = 16; o; o >>= 1) m = fmaxf(m, __shfl_xor_sync(~0u, m, o));
        float e0 = __expf(x.x - m), e1 = __expf(x.y - m), e2 = __expf(x.z - m), e3 = __expf(x.w - m);
        float s = e0 + e1 + e2 + e3;
#pragma unroll
        for (int o = 16; o; o >>= 1) s += __shfl_xor_sync(~0u, s, o);
        float inv = 1.f / s;
        *(float4*)(g_kl + (size_t)rk * 128 + lane * 4) = make_float4(e0 * inv, e1 * inv, e2 * inv, e3 * inv);
        float4 bt;
        bt.x = (fminf(x.x, 0.f) - log1pf(__expf(-fabsf(x.x)))) * 0.0625f;
        bt.y = (fminf(x.y, 0.f) - log1pf(__expf(-fabsf(x.y)))) * 0.0625f;
        bt.z = (fminf(x.z, 0.f) - log1pf(__expf(-fabsf(x.z)))) * 0.0625f;
        bt.w = (fminf(x.w, 0.f) - log1pf(__expf(-fabsf(x.w)))) * 0.0625f;
        *(float4*)(g_bt + (size_t)rk * 128 + lane * 4) = bt;
    }
}

// ---------------- pairwise-dot (unchanged) ----------------------------------
__global__ void __launch_bounds__(256) pairdot_kernel(int isP)
{
    extern __shared__ float sm[];
    float* Xs = sm;
    float* Ys = sm + 8192;
    const int blk = blockIdx.x;
    const int tid = threadIdx.x;
    const float* xbase; const float* ybase; float* out; int ldx, ldy;
    if (isP) {
        int b = blk >> 8, h = (blk >> 4) & 15, cn = blk & 15;
        int tok0 = b * 1024 + cn * 64;
        xbase = g_ql + (size_t)tok0 * HIDN + h * 128; ldx = HIDN;
        ybase = g_kl + (size_t)tok0 * KVD + (h >> 2) * 128; ldy = KVD;
        out = g_P + (size_t)blk * 4096;
    } else {
        int b = blk >> 6, kv = (blk >> 4) & 3, cn = blk & 15;
        int tok0 = b * 1024 + cn * 64;
        xbase = g_kl + (size_t)tok0 * KVD + kv * 128; ldx = KVD;
        ybase = xbase; ldy = KVD;
        out = g_A + (size_t)blk * 4096;
    }
    for (int i = tid * 4; i < 8192; i += 1024) {
        int r = i >> 7, c = i & 127;
        *(float4*)(Xs + i) = *(const float4*)(xbase + (size_t)r * ldx + c);
        *(float4*)(Ys + i) = *(const float4*)(ybase + (size_t)r * ldy + c);
    }
    __syncthreads();
    const int a0 = (tid >> 4) * 4, b0 = (tid & 15) * 4;
    float s4[4][4];
#pragma unroll
    for (int i = 0; i < 4; i++)
#pragma unroll
        for (int j = 0; j < 4; j++) s4[i][j] = 0.f;
    for (int d = 0; d < 128; d += 4) {
        float4 qa[4], kb[4];
#pragma unroll
        for (int i = 0; i < 4; i++) qa[i] = *(const float4*)(Xs + (a0 + i) * 128 + d);
#pragma unroll
        for (int j = 0; j < 4; j++) kb[j] = *(const float4*)(Ys + (b0 + j) * 128 + d);
#pragma unroll
        for (int i = 0; i < 4; i++)
#pragma unroll
            for (int j = 0; j < 4; j++)
                s4[i][j] += qa[i].x * kb[j].x + qa[i].y * kb[j].y + qa[i].z * kb[j].z + qa[i].w * kb[j].w;
    }
#pragma unroll
    for (int i = 0; i < 4; i++)
#pragma unroll
        for (int j = 0; j < 4; j++) {
            int t = a0 + i, s = b0 + j;
            bool keep = isP ? (s <= t) : (s < t);
            out[t * 64 + s] = keep ? s4[i][j] : 0.f;
        }
}

// ---------------- M inverse precompute (plain M, unchanged) ------------------
__global__ void __launch_bounds__(128) minv_kernel()
{
    extern __shared__ float ms[];
    float* As = ms;
    float* Xs = ms + 4096;
    float* bs = Xs + 8320;
    const int tid = threadIdx.x;
    const int c0 = blockIdx.x * 2, ach = blockIdx.y;
    const int b = ach >> 6, kv = (ach >> 4) & 3, cn = ach & 15;
    const int tok0 = b * 1024 + cn * 64;

    for (int i = tid * 4; i < 4096; i += 512)
        *(float4*)(As + i) = *(const float4*)(g_A + (size_t)ach * 4096 + i);
    {
        int c = tid >> 6, t = tid & 63;
        bs[c * 64 + t] = g_bt[(size_t)(tok0 + t) * KVD + kv * 128 + c0 + c];
    }
    __syncthreads();

    const int c = tid >> 6, s = tid & 63;
    float* Xc = Xs + c * 4160;
    Xc[s * 65 + s] = 1.f;
    for (int i = s + 1; i < 64; i++) {
        float acc = 0.f;
        for (int p = s; p < i; p++) acc += As[i * 64 + p] * Xc[p * 65 + s];
        Xc[i * 65 + s] = -bs[c * 64 + i] * acc;
    }
    __nv_bfloat16* dst = g_M + (size_t)((ach * 128 + c0 + c) * 64) * 64 + s;
    for (int t = 0; t < 64; t++) {
        float val = (t > s) ? Xc[t * 65 + s] : (t == s ? 1.f : 0.f);
        dst[t * 64] = __float2bfloat16(val);
    }
}

// ---------------- flash attention (epilogue writes tf32-rounded) -------------
#define FQS 132
#define FKS 132
#define FVS 136
#define FSS 68

__global__ void __launch_bounds__(256) flash_kernel(
    const float* __restrict__ q, const float* __restrict__ k,
    const float* __restrict__ v, float* __restrict__ comb)
{
    extern __shared__ float fsm[];
    float* Qs = fsm;
    float* Ks = Qs + 64 * FQS;
    float* Vs = Ks + 64 * FKS;
    float* Ss = Vs + 64 * FVS;
    float* msh = Ss + 64 * FSS;
    float* lsh = msh + 64;
    float* csh = lsh + 64;
    const int tid = threadIdx.x, lane = tid & 31, warp = tid >> 5;
    const int qt = 15 - (blockIdx.x & 15);
    const int bh = blockIdx.y;
    const int b = bh >> 4, h = bh & 15, kvh = h >> 2;
    const float scale = 0.08838834764831845f;
    {
        const float* qb = q + (size_t)(b * 1024 + qt * 64) * HIDN + h * 128;
        for (int i = tid; i < 2048; i += 256) {
            int r = i >> 5, c4 = (i & 31) * 4;
            float4 t4 = *(const float4*)(qb + (size_t)r * HIDN + c4);
            Qs[r * FQS + c4 + 0] = f2tf_f(t4.x * scale);
            Qs[r * FQS + c4 + 1] = f2tf_f(t4.y * scale);
            Qs[r * FQS + c4 + 2] = f2tf_f(t4.z * scale);
            Qs[r * FQS + c4 + 3] = f2tf_f(t4.w * scale);
        }
    }
    if (tid < 64) { msh[tid] = -1e30f; lsh[tid] = 0.f; }
    const int wr2 = (warp >> 2) * 32, wc2 = (warp & 3) * 32;
    float oc[2][4][4];
#pragma unroll
    for (int mt = 0; mt < 2; mt++)
#pragma unroll
        for (int nt = 0; nt < 4; nt++)
#pragma unroll
            for (int i = 0; i < 4; i++) oc[mt][nt][i] = 0.f;

    for (int j = 0; j <= qt; j++) {
        __syncthreads();
        {
            const float* kb = k + (size_t)(b * 1024 + j * 64) * KVD + kvh * 128;
            const float* vb = v + (size_t)(b * 1024 + j * 64) * KVD + kvh * 128;
            for (int i = tid; i < 2048; i += 256) {
                int r = i >> 5, c4 = (i & 31) * 4;
                float4 k4 = *(const float4*)(kb + (size_t)r * KVD + c4);
                Ks[r * FKS + c4 + 0] = f2tf_f(k4.x); Ks[r * FKS + c4 + 1] = f2tf_f(k4.y);
                Ks[r * FKS + c4 + 2] = f2tf_f(k4.z); Ks[r * FKS + c4 + 3] = f2tf_f(k4.w);
                float4 v4 = *(const float4*)(vb + (size_t)r * KVD + c4);
                Vs[r * FVS + c4 + 0] = f2tf_f(v4.x); Vs[r * FVS + c4 + 1] = f2tf_f(v4.y);
                Vs[r * FVS + c4 + 2] = f2tf_f(v4.z); Vs[r * FVS + c4 + 3] = f2tf_f(v4.w);
            }
        }
        __syncthreads();
        {
            float sc[2][2][4];
#pragma unroll
            for (int mt = 0; mt < 2; mt++)
#pragma unroll
                for (int nt = 0; nt < 2; nt++)
#pragma unroll
                    for (int i = 0; i < 4; i++) sc[mt][nt][i] = 0.f;
            const int swr = (warp >> 2) * 32, swc = (warp & 3) * 16;
            const int r0 = swr + (lane >> 2);
#pragma unroll
            for (int ks = 0; ks < 16; ks++) {
                const int kc = ks * 8 + (lane & 3);
                unsigned a[2][4], bf[2][2];
#pragma unroll
                for (int mt = 0; mt < 2; mt++) {
                    a[mt][0] = __float_as_uint(Qs[(r0 + mt * 16) * FQS + kc]);
                    a[mt][1] = __float_as_uint(Qs[(r0 + mt * 16 + 8) * FQS + kc]);
                    a[mt][2] = __float_as_uint(Qs[(r0 + mt * 16) * FQS + kc + 4]);
                    a[mt][3] = __float_as_uint(Qs[(r0 + mt * 16 + 8) * FQS + kc + 4]);
                }
                const int nc = swc + (lane >> 2);
#pragma unroll
                for (int nt = 0; nt < 2; nt++) {
                    bf[nt][0] = __float_as_uint(Ks[(nc + nt * 8) * FKS + kc]);
                    bf[nt][1] = __float_as_uint(Ks[(nc + nt * 8) * FKS + kc + 4]);
                }
#pragma unroll
                for (int mt = 0; mt < 2; mt++)
#pragma unroll
                    for (int nt = 0; nt < 2; nt++)
                        mma8(sc[mt][nt], a[mt], bf[nt]);
            }
#pragma unroll
            for (int mt = 0; mt < 2; mt++)
#pragma unroll
                for (int nt = 0; nt < 2; nt++) {
                    int rr = swr + mt * 16 + (lane >> 2);
                    int cc = swc + nt * 8 + 2 * (lane & 3);
                    Ss[rr * FSS + cc] = sc[mt][nt][0];
                    Ss[rr * FSS + cc + 1] = sc[mt][nt][1];
                    Ss[(rr + 8) * FSS + cc] = sc[mt][nt][2];
                    Ss[(rr + 8) * FSS + cc + 1] = sc[mt][nt][3];
                }
        }
        __syncthreads();
        {
            const int row = tid >> 2, sub = tid & 3;
            float* srow = Ss + row * FSS + sub * 16;
            float pv[16];
            float mx = -1e30f;
#pragma unroll
            for (int ii = 0; ii < 16; ii++) {
                float x = srow[ii];
                if (j == qt && (sub * 16 + ii) > row) x = -1e30f;
                pv[ii] = x;
                mx = fmaxf(mx, x);
            }
            mx = fmaxf(mx, __shfl_xor_sync(~0u, mx, 1));
            mx = fmaxf(mx, __shfl_xor_sync(~0u, mx, 2));
            float mold = msh[row];
            float mnew = fmaxf(mx, mold);
            float cf = __expf(mold - mnew);
            float lsum = 0.f;
#pragma unroll
            for (int ii = 0; ii < 16; ii++) {
                float p = __expf(pv[ii] - mnew);
                srow[ii] = f2tf_f(p);
                lsum += p;
            }
            lsum += __shfl_xor_sync(~0u, lsum, 1);
            lsum += __shfl_xor_sync(~0u, lsum, 2);
            if (sub == 0) {
                msh[row] = mnew;
                lsh[row] = lsh[row] * cf + lsum;
                csh[row] = cf;
            }
        }
        __syncthreads();
        {
            const int rA = wr2 + (lane >> 2);
#pragma unroll
            for (int mt = 0; mt < 2; mt++) {
                float cl = csh[rA + mt * 16];
                float ch = csh[rA + mt * 16 + 8];
#pragma unroll
                for (int nt = 0; nt < 4; nt++) {
                    oc[mt][nt][0] *= cl; oc[mt][nt][1] *= cl;
                    oc[mt][nt][2] *= ch; oc[mt][nt][3] *= ch;
                }
            }
#pragma unroll
            for (int ks = 0; ks < 8; ks++) {
                const int kc = ks * 8 + (lane & 3);
                unsigned a[2][4], bf[4][2];
#pragma unroll
                for (int mt = 0; mt < 2; mt++) {
                    a[mt][0] = __float_as_uint(Ss[(rA + mt * 16) * FSS + kc]);
                    a[mt][1] = __float_as_uint(Ss[(rA + mt * 16 + 8) * FSS + kc]);
                    a[mt][2] = __float_as_uint(Ss[(rA + mt * 16) * FSS + kc + 4]);
                    a[mt][3] = __float_as_uint(Ss[(rA + mt * 16 + 8) * FSS + kc + 4]);
                }
                const int nc = wc2 + (lane >> 2);
#pragma unroll
                for (int nt = 0; nt < 4; nt++) {
                    bf[nt][0] = __float_as_uint(Vs[kc * FVS + nc + nt * 8]);
                    bf[nt][1] = __float_as_uint(Vs[(kc + 4) * FVS + nc + nt * 8]);
                }
#pragma unroll
                for (int mt = 0; mt < 2; mt++)
#pragma unroll
                    for (int nt = 0; nt < 4; nt++)
                        mma8(oc[mt][nt], a[mt], bf[nt]);
            }
        }
    }
#pragma unroll
    for (int mt = 0; mt < 2; mt++) {
        int r1 = wr2 + mt * 16 + (lane >> 2);
        int r2 = r1 + 8;
        float il1 = 0.5f / lsh[r1];
        float il2 = 0.5f / lsh[r2];
        size_t base1 = (size_t)(b * 1024 + qt * 64 + r1) * HIDN + h * 128;
        size_t base2 = (size_t)(b * 1024 + qt * 64 + r2) * HIDN + h * 128;
#pragma unroll
        for (int nt = 0; nt < 4; nt++) {
            int col = wc2 + nt * 8 + 2 * (lane & 3);
            *(float2*)(comb + base1 + col) = make_float2(oc[mt][nt][0] * il1, oc[mt][nt][1] * il1);
            *(float2*)(comb + base2 + col) = make_float2(oc[mt][nt][2] * il2, oc[mt][nt][3] * il2);
        }
    }
}

// ---------------- delta-rule: EXACT round-9 structure + register-S -----------
// 128 blocks x 128 threads, ONE channel per block
// stage floats: K 64*132=8448 | M bf16 64x72 = 2304 fl | v 64 | b 64
#define DSTG5 10880

__device__ __forceinline__ void delta_prefetch5(float* base, int gn, int c0, int tid)
{
    int bb = gn >> 8, hh = (gn >> 4) & 15, cn = gn & 15, kv = hh >> 2;
    int tok0 = bb * 1024 + cn * 64;
    int ach = (bb * 4 + kv) * 16 + cn;
    float* K_ = base;
    __nv_bfloat16* Mb = (__nv_bfloat16*)(base + 8448);
    float* v_ = base + 10752;
    float* b_ = base + 10816;
#pragma unroll
    for (int i = 0; i < 16; i++) {
        int jj = tid + 128 * i; int tr = jj >> 5, cc = (jj & 31) << 2;
        cpa16(K_ + tr * 132 + cc, g_kl + (size_t)(tok0 + tr) * KVD + kv * 128 + cc);
    }
#pragma unroll
    for (int i = 0; i < 4; i++) {
        int jj = tid + 128 * i; int row = jj >> 3, k8 = (jj & 7) * 8;
        cpa16(Mb + row * 72 + k8,
              g_M + ((size_t)(ach * 128 + c0) * 64 + row) * 64 + k8);
    }
    if (tid < 64) {
        cpa4(v_ + tid, g_v + (size_t)(tok0 + tid) * KVD + kv * 128 + c0);
    } else {
        int tt = tid - 64;
        cpa4(b_ + tt, g_bt + (size_t)(tok0 + tt) * KVD + kv * 128 + c0);
    }
}

__global__ void __launch_bounds__(128) delta_kernel()
{
    extern __shared__ float dsm[];
    float* Ssh = dsm + 2 * DSTG5;   // 128
    float* r_ = Ssh + 128;          // 68
    float* u_ = r_ + 68;            // 68
    const int tid = threadIdx.x;
    const int c0 = blockIdx.x;      // one channel
    const int t = tid >> 1, hf = tid & 1;

    float sreg = 0.f;               // S[d=tid] carried in register
    Ssh[tid] = 0.f;
    delta_prefetch5(dsm, 0, c0, tid);
    CPA_COMMIT();
    __syncthreads();

    for (int gc = 0; gc < NGC; gc++) {
        if (gc + 1 < NGC) delta_prefetch5(dsm + ((gc + 1) & 1) * DSTG5, gc + 1, c0, tid);
        CPA_COMMIT();
        CPA_WAIT1();
        __syncthreads();

        float* base = dsm + (gc & 1) * DSTG5;
        float* K_ = base;
        const __nv_bfloat16* Mb = (const __nv_bfloat16*)(base + 8448);
        float* v_ = base + 10752;
        float* b_ = base + 10816;

        // S0 snapshot [gc][k=tid][c0] from register
        g_S0T[((size_t)gc * 128 + tid) * 128 + c0] = sreg;

        // phase B: token t, half hf; mm = k_t . S ; r = beta*(v - mm)
        {
            float mm = 0.f;
            const float* krow = K_ + t * 132 + hf * 64;
            const float* scol = Ssh + hf * 64;
#pragma unroll
            for (int d = 0; d < 64; d += 4) {
                float4 k4 = *(const float4*)(krow + d);
                float4 s4 = *(const float4*)(scol + d);
                mm += k4.x * s4.x + k4.y * s4.y + k4.z * s4.z + k4.w * s4.w;
            }
            mm += __shfl_xor_sync(~0u, mm, 1);
            if (hf == 0) r_[t] = b_[t] * (v_[t] - mm);
        }
        __syncthreads();

        // u = M r, half-row each, shfl combine
        {
            float u = 0.f;
            const __nv_bfloat16* mrow = Mb + t * 72 + hf * 32;
            const float* rr = r_ + hf * 32;
#pragma unroll
            for (int j = 0; j < 4; j++) {
                uint4 w = *(const uint4*)(mrow + j * 8);
                float2 f0 = __bfloat1622float2(*(__nv_bfloat162*)&w.x);
                float2 f1 = __bfloat1622float2(*(__nv_bfloat162*)&w.y);
                float2 f2 = __bfloat1622float2(*(__nv_bfloat162*)&w.z);
                float2 f3 = __bfloat1622float2(*(__nv_bfloat162*)&w.w);
                float4 ra = *(const float4*)(rr + j * 8);
                float4 rb = *(const float4*)(rr + j * 8 + 4);
                u += f0.x * ra.x + f0.y * ra.y + f1.x * ra.z + f1.y * ra.w
                   + f2.x * rb.x + f2.y * rb.y + f3.x * rb.z + f3.y * rb.w;
            }
            u += __shfl_xor_sync(~0u, u, 1);
            if (hf == 0) {
                u_[t] = u;
                g_U[((size_t)gc * 64 + t) * 128 + c0] = u;
            }
        }
        __syncthreads();

        // phase E: sreg += sum_t2 K[t2][tid] * u[t2]; mirror to smem
        {
#pragma unroll 8
            for (int t2 = 0; t2 < 64; t2++)
                sreg += K_[t2 * 132 + tid] * u_[t2];
            Ssh[tid] = sreg;
        }
        __syncthreads();
    }
}

// ---------------- okernel (writes tf32-rounded comb) --------------------------
__global__ void __launch_bounds__(256) okernel(float* __restrict__ comb)
{
    extern __shared__ float osm[];
    float* Qs = osm;               // 64*132
    float* Ps = Qs + 8448;         // 64*68
    float* Us = Ps + 4352;         // 64*132
    float* S0p = Us + 8448;        // 32*132
    const int gc = blockIdx.x;
    const int b = gc >> 8, h = (gc >> 4) & 15, cn = gc & 15;
    const int tok0 = b * 1024 + cn * 64;
    const int tid = threadIdx.x;

    for (int i = tid; i < 2048; i += 256) {
        int r = i >> 5, c4 = (i & 31) * 4;
        *(float4*)(Qs + r * 132 + c4) =
            *(const float4*)(g_ql + (size_t)(tok0 + r) * HIDN + h * 128 + c4);
    }
    for (int i = tid; i < 1024; i += 256) {
        int r = i >> 4, c4 = (i & 15) * 4;
        *(float4*)(Ps + r * 68 + c4) = *(const float4*)(g_P + (size_t)gc * 4096 + i * 4);
    }
    for (int i = tid; i < 2048; i += 256) {
        int s = i >> 5, c4 = (i & 31) * 4;
        *(float4*)(Us + s * 132 + c4) = *(const float4*)(g_U + ((size_t)gc * 64 + s) * 128 + c4);
    }
    __syncthreads();

    const int t0 = (tid >> 4) * 4, cc0 = (tid & 15) * 8;
    float acc[4][8];
#pragma unroll
    for (int i = 0; i < 4; i++)
#pragma unroll
        for (int j = 0; j < 8; j++) acc[i][j] = 0.f;
    for (int s = 0; s < 64; s++) {
        float4 ua = *(const float4*)(Us + s * 132 + cc0);
        float4 ub = *(const float4*)(Us + s * 132 + cc0 + 4);
#pragma unroll
        for (int i = 0; i < 4; i++) {
            float p = Ps[(t0 + i) * 68 + s];
            acc[i][0] += p * ua.x; acc[i][1] += p * ua.y;
            acc[i][2] += p * ua.z; acc[i][3] += p * ua.w;
            acc[i][4] += p * ub.x; acc[i][5] += p * ub.y;
            acc[i][6] += p * ub.z; acc[i][7] += p * ub.w;
        }
    }
    for (int kp = 0; kp < 128; kp += 32) {
        __syncthreads();
        for (int i = tid; i < 1024; i += 256) {
            int k = i >> 5, c4 = (i & 31) * 4;
            *(float4*)(S0p + k * 132 + c4) =
                *(const float4*)(g_S0T + ((size_t)gc * 128 + kp + k) * 128 + c4);
        }
        __syncthreads();
        for (int k = 0; k < 32; k++) {
            float4 sa = *(const float4*)(S0p + k * 132 + cc0);
            float4 sb = *(const float4*)(S0p + k * 132 + cc0 + 4);
#pragma unroll
            for (int i = 0; i < 4; i++) {
                float qv = Qs[(t0 + i) * 132 + kp + k];
                acc[i][0] += qv * sa.x; acc[i][1] += qv * sa.y;
                acc[i][2] += qv * sa.z; acc[i][3] += qv * sa.w;
                acc[i][4] += qv * sb.x; acc[i][5] += qv * sb.y;
                acc[i][6] += qv * sb.z; acc[i][7] += qv * sb.w;
            }
        }
    }
#pragma unroll
    for (int i = 0; i < 4; i++) {
        float* dst = comb + (size_t)(tok0 + t0 + i) * HIDN + h * 128 + cc0;
        float4 o1 = *(float4*)dst;
        float4 o2 = *(float4*)(dst + 4);
        o1.x = f2tf_f(o1.x + 0.5f * acc[i][0]); o1.y = f2tf_f(o1.y + 0.5f * acc[i][1]);
        o1.z = f2tf_f(o1.z + 0.5f * acc[i][2]); o1.w = f2tf_f(o1.w + 0.5f * acc[i][3]);
        o2.x = f2tf_f(o2.x + 0.5f * acc[i][4]); o2.y = f2tf_f(o2.y + 0.5f * acc[i][5]);
        o2.z = f2tf_f(o2.z + 0.5f * acc[i][6]); o2.w = f2tf_f(o2.w + 0.5f * acc[i][7]);
        *(float4*)dst = o1; *(float4*)(dst + 4) = o2;
    }
}

// ---------------- launch -----------------------------------------------------
extern "C" void kernel_launch(void* const* d_in, const int* in_sizes, int n_in,
                              void* d_out, int out_size)
{
    const float* hs = (const float*)d_in[0];
    const float* Wq = (const float*)d_in[1];
    const float* Wk = (const float*)d_in[2];
    const float* Wv = (const float*)d_in[3];
    const float* Wo = (const float*)d_in[4];
    float* out = (float*)d_out;

    float *p_q, *p_k, *p_v, *p_comb;
    float *p_hsr, *p_wqr, *p_wkr, *p_wvr, *p_wor;
    cudaGetSymbolAddress((void**)&p_q, g_q);
    cudaGetSymbolAddress((void**)&p_k, g_k);
    cudaGetSymbolAddress((void**)&p_v, g_v);
    cudaGetSymbolAddress((void**)&p_comb, g_comb);
    cudaGetSymbolAddress((void**)&p_hsr, g_hsr);
    cudaGetSymbolAddress((void**)&p_wqr, g_wqr);
    cudaGetSymbolAddress((void**)&p_wkr, g_wkr);
    cudaGetSymbolAddress((void**)&p_wvr, g_wvr);
    cudaGetSymbolAddress((void**)&p_wor, g_wor);

    const int gemm_smem = 2 * GSTG * 4;
    const int pair_smem = 8192 * 2 * 4;
    const int flash_smem = (64 * FQS + 64 * FKS + 64 * FVS + 64 * FSS + 192) * 4;
    const int delta_smem = (2 * DSTG5 + 128 + 68 + 68) * 4;
    const int minv_smem = (4096 + 8320 + 128) * 4;
    const int o_smem = (8448 + 4352 + 8448 + 32 * 132) * 4;
    cudaFuncSetAttribute(mma_gemm, cudaFuncAttributeMaxDynamicSharedMemorySize, gemm_smem);
    cudaFuncSetAttribute(pairdot_kernel, cudaFuncAttributeMaxDynamicSharedMemorySize, pair_smem);
    cudaFuncSetAttribute(flash_kernel, cudaFuncAttributeMaxDynamicSharedMemorySize, flash_smem);
    cudaFuncSetAttribute(delta_kernel, cudaFuncAttributeMaxDynamicSharedMemorySize, delta_smem);
    cudaFuncSetAttribute(minv_kernel, cudaFuncAttributeMaxDynamicSharedMemorySize, minv_smem);
    cudaFuncSetAttribute(okernel, cudaFuncAttributeMaxDynamicSharedMemorySize, o_smem);

    // pre-round GEMM operands to tf32
    round_kernel<<<(TOK * HIDN / 4 + 255) / 256, 256>>>(hs, p_hsr, TOK * HIDN / 4);
    round_kernel<<<(HIDN * HIDN / 4 + 255) / 256, 256>>>(Wq, p_wqr, HIDN * HIDN / 4);
    round_kernel<<<(HIDN * KVD / 4 + 255) / 256, 256>>>(Wk, p_wkr, HIDN * KVD / 4);
    round_kernel<<<(HIDN * KVD / 4 + 255) / 256, 256>>>(Wv, p_wvr, HIDN * KVD / 4);
    round_kernel<<<(HIDN * HIDN / 4 + 255) / 256, 256>>>(Wo, p_wor, HIDN * HIDN / 4);

    mma_gemm<<<dim3(16, 16), 256, gemm_smem>>>(p_hsr, p_wqr, p_q, TOK, HIDN, HIDN);
    mma_gemm<<<dim3(4, 16), 256, gemm_smem>>>(p_hsr, p_wkr, p_k, TOK, KVD, HIDN);
    mma_gemm<<<dim3(4, 16), 256, gemm_smem>>>(p_hsr, p_wvr, p_v, TOK, KVD, HIDN);
    act_kernel<<<5120, 256>>>();
    pairdot_kernel<<<NACH, 256, pair_smem>>>(0);
    minv_kernel<<<dim3(64, 128), 128, minv_smem>>>();
    pairdot_kernel<<<NGC, 256, pair_smem>>>(1);
    flash_kernel<<<dim3(16, 32), 256, flash_smem>>>(p_q, p_k, p_v, p_comb);
    delta_kernel<<<128, 128, delta_smem>>>();
    okernel<<<NGC, 256, o_smem>>>(p_comb);
    mma_gemm<<<dim3(16, 16), 256, gemm_smem>>>(p_comb, p_wor, out, TOK, HIDN, HIDN);
}

// round 14
// speedup vs baseline: 1.2589x; 1.0314x over previous
#include <cuda_runtime.h>
#include <cuda_bf16.h>
#include <math.h>

#define TOK 2048
#define HIDN 2048
#define KVD 512
#define CHK 64
#define NGC 512
#define NACH 128

__device__ float g_q[TOK * HIDN];
__device__ float g_k[TOK * KVD];
__device__ float g_v[TOK * KVD];
__device__ float g_ql[TOK * HIDN];
__device__ float g_kl[TOK * KVD];
__device__ float g_bt[TOK * KVD];
__device__ float g_A[NACH * CHK * CHK];
__device__ float g_P[NGC * CHK * CHK];
__device__ float g_comb[TOK * HIDN];
__device__ __nv_bfloat16 g_M[(size_t)NACH * 128 * CHK * CHK];
__device__ float g_S0T[(size_t)NGC * 128 * 128];   // [gc][k][c]
__device__ float g_U[(size_t)NGC * CHK * 128];     // [gc][t][c]
__device__ float g_hsr[TOK * HIDN];
__device__ float g_wqr[HIDN * HIDN];
__device__ float g_wkr[HIDN * KVD];
__device__ float g_wvr[HIDN * KVD];
__device__ float g_wor[HIDN * HIDN];

__device__ __forceinline__ unsigned f2tf(float x) {
    unsigned u; asm("cvt.rna.tf32.f32 %0, %1;" : "=r"(u) : "f"(x)); return u;
}
__device__ __forceinline__ float f2tf_f(float x) { return __uint_as_float(f2tf(x)); }

__device__ __forceinline__ void mma8(float c[4], const unsigned a[4], const unsigned b[2]) {
    asm volatile(
        "mma.sync.aligned.m16n8k8.row.col.f32.tf32.tf32.f32 "
        "{%0,%1,%2,%3}, {%4,%5,%6,%7}, {%8,%9}, {%0,%1,%2,%3};"
        : "+f"(c[0]), "+f"(c[1]), "+f"(c[2]), "+f"(c[3])
        : "r"(a[0]), "r"(a[1]), "r"(a[2]), "r"(a[3]), "r"(b[0]), "r"(b[1]));
}
__device__ __forceinline__ void cpa16(void* dst, const void* src) {
    unsigned d = (unsigned)__cvta_generic_to_shared(dst);
    asm volatile("cp.async.ca.shared.global [%0], [%1], 16;" :: "r"(d), "l"(src) : "memory");
}
__device__ __forceinline__ void cpa4(void* dst, const void* src) {
    unsigned d = (unsigned)__cvta_generic_to_shared(dst);
    asm volatile("cp.async.ca.shared.global [%0], [%1], 4;" :: "r"(d), "l"(src) : "memory");
}
#define CPA_COMMIT() asm volatile("cp.async.commit_group;" ::: "memory")
#define CPA_WAIT1()  asm volatile("cp.async.wait_group 1;" ::: "memory")

// ---------------- rounding pre-pass ------------------------------------------
__global__ void __launch_bounds__(256) round_kernel(
    const float* __restrict__ src, float* __restrict__ dst, int n4)
{
    int i = blockIdx.x * 256 + threadIdx.x;
    if (i < n4) {
        float4 x = ((const float4*)src)[i];
        x.x = f2tf_f(x.x); x.y = f2tf_f(x.y);
        x.z = f2tf_f(x.z); x.w = f2tf_f(x.w);
        ((float4*)dst)[i] = x;
    }
}

// ------------------------ tf32 MMA GEMM --------------------------------------
#define GAS 36
#define GBS 136
#define GSTG (128 * GAS + 32 * GBS)

__device__ __forceinline__ void gemm_issue(
    const float* __restrict__ A, const float* __restrict__ B,
    float* As, float* Bs, int bRow, int bCol, int k0, int K, int N, int tid)
{
#pragma unroll
    for (int i = 0; i < 4; i++) {
        int lin = tid + 256 * i;
        int r = lin >> 3, c4 = (lin & 7) << 2;
        cpa16(As + r * GAS + c4, A + (size_t)(bRow + r) * K + k0 + c4);
    }
#pragma unroll
    for (int i = 0; i < 4; i++) {
        int lin = tid + 256 * i;
        int r = lin >> 5, c4 = (lin & 31) << 2;
        cpa16(Bs + r * GBS + c4, B + (size_t)(k0 + r) * N + bCol + c4);
    }
    CPA_COMMIT();
}

__global__ void __launch_bounds__(256) mma_gemm(
    const float* __restrict__ A, const float* __restrict__ B,
    float* __restrict__ C, int M, int N, int K)
{
    extern __shared__ float gsm[];
    const int tid = threadIdx.x, lane = tid & 31, warp = tid >> 5;
    const int bRow = blockIdx.y * 128, bCol = blockIdx.x * 128;
    const int wr = (warp >> 2) * 64, wc = (warp & 3) * 32;
    float acc[4][4][4];
#pragma unroll
    for (int mt = 0; mt < 4; mt++)
#pragma unroll
        for (int nt = 0; nt < 4; nt++)
#pragma unroll
            for (int i = 0; i < 4; i++) acc[mt][nt][i] = 0.f;

    gemm_issue(A, B, gsm, gsm + 128 * GAS, bRow, bCol, 0, K, N, tid);
    gemm_issue(A, B, gsm + GSTG, gsm + GSTG + 128 * GAS, bRow, bCol, 32, K, N, tid);

    const int iters = K / 32;
    for (int it = 0; it < iters; it++) {
        CPA_WAIT1();
        __syncthreads();
        float* As = gsm + (it & 1) * GSTG;
        float* Bs = As + 128 * GAS;
#pragma unroll
        for (int kk = 0; kk < 4; kk++) {
            unsigned a[4][4], bfr[4][2];
            const int kc = kk * 8 + (lane & 3);
            const int r0 = wr + (lane >> 2);
#pragma unroll
            for (int mt = 0; mt < 4; mt++) {
                a[mt][0] = __float_as_uint(As[(r0 + mt * 16) * GAS + kc]);
                a[mt][1] = __float_as_uint(As[(r0 + mt * 16 + 8) * GAS + kc]);
                a[mt][2] = __float_as_uint(As[(r0 + mt * 16) * GAS + kc + 4]);
                a[mt][3] = __float_as_uint(As[(r0 + mt * 16 + 8) * GAS + kc + 4]);
            }
            const int nc0 = wc + (lane >> 2);
#pragma unroll
            for (int nt = 0; nt < 4; nt++) {
                bfr[nt][0] = __float_as_uint(Bs[kc * GBS + nc0 + nt * 8]);
                bfr[nt][1] = __float_as_uint(Bs[(kc + 4) * GBS + nc0 + nt * 8]);
            }
#pragma unroll
            for (int mt = 0; mt < 4; mt++)
#pragma unroll
                for (int nt = 0; nt < 4; nt++)
                    mma8(acc[mt][nt], a[mt], bfr[nt]);
        }
        __syncthreads();
        if (it + 2 < iters) {
            float* As2 = gsm + (it & 1) * GSTG;
            gemm_issue(A, B, As2, As2 + 128 * GAS, bRow, bCol, (it + 2) * 32, K, N, tid);
        } else {
            CPA_COMMIT();
        }
    }
    const int r0 = bRow + wr + (lane >> 2);
    const int c0 = bCol + wc + 2 * (lane & 3);
#pragma unroll
    for (int mt = 0; mt < 4; mt++)
#pragma unroll
        for (int nt = 0; nt < 4; nt++) {
            float* p1 = C + (size_t)(r0 + mt * 16) * N + c0 + nt * 8;
            float* p2 = C + (size_t)(r0 + mt * 16 + 8) * N + c0 + nt * 8;
            *(float2*)p1 = make_float2(acc[mt][nt][0], acc[mt][nt][1]);
            *(float2*)p2 = make_float2(acc[mt][nt][2], acc[mt][nt][3]);
        }
}

// ---------------- activations (unchanged) -----------------------------------
__global__ void __launch_bounds__(256) act_kernel()
{
    int wg = (blockIdx.x * 256 + threadIdx.x) >> 5;
    int lane = threadIdx.x & 31;
    if (wg < 32768) {
        float4 x = *(const float4*)(g_q + (size_t)wg * 128 + lane * 4);
        float m = fmaxf(fmaxf(x.x, x.y), fmaxf(x.z, x.w));
#pragma unroll
        for (int o = 16; o; o >>= 1) m = fmaxf(m, __shfl_xor_sync(~0u, m, o));
        float e0 = __expf(x.x - m), e1 = __expf(x.y - m), e2 = __expf(x.z - m), e3 = __expf(x.w - m);
        float s = e0 + e1 + e2 + e3;
#pragma unroll
        for (int o = 16; o; o >>= 1) s += __shfl_xor_sync(~0u, s, o);
        float inv = 1.f / s;
        *(float4*)(g_ql + (size_t)wg * 128 + lane * 4) = make_float4(e0 * inv, e1 * inv, e2 * inv, e3 * inv);
    } else {
        int rk = wg - 32768;
        if (rk >= 8192) return;
        float4 x = *(const float4*)(g_k + (size_t)rk * 128 + lane * 4);
        float m = fmaxf(fmaxf(x.x, x.y), fmaxf(x.z, x.w));
#pragma unroll
        for (int o = 16; o; o >>= 1) m = fmaxf(m, __shfl_xor_sync(~0u, m, o));
        float e0 = __expf(x.x - m), e1 = __expf(x.y - m), e2 = __expf(x.z - m), e3 = __expf(x.w - m);
        float s = e0 + e1 + e2 + e3;
#pragma unroll
        for (int o = 16; o; o >>= 1) s += __shfl_xor_sync(~0u, s, o);
        float inv = 1.f / s;
        *(float4*)(g_kl + (size_t)rk * 128 + lane * 4) = make_float4(e0 * inv, e1 * inv, e2 * inv, e3 * inv);
        float4 bt;
        bt.x = (fminf(x.x, 0.f) - log1pf(__expf(-fabsf(x.x)))) * 0.0625f;
        bt.y = (fminf(x.y, 0.f) - log1pf(__expf(-fabsf(x.y)))) * 0.0625f;
        bt.z = (fminf(x.z, 0.f) - log1pf(__expf(-fabsf(x.z)))) * 0.0625f;
        bt.w = (fminf(x.w, 0.f) - log1pf(__expf(-fabsf(x.w)))) * 0.0625f;
        *(float4*)(g_bt + (size_t)rk * 128 + lane * 4) = bt;
    }
}

// ---------------- pairwise-dot (unchanged) ----------------------------------
__global__ void __launch_bounds__(256) pairdot_kernel(int isP)
{
    extern __shared__ float sm[];
    float* Xs = sm;
    float* Ys = sm + 8192;
    const int blk = blockIdx.x;
    const int tid = threadIdx.x;
    const float* xbase; const float* ybase; float* out; int ldx, ldy;
    if (isP) {
        int b = blk >> 8, h = (blk >> 4) & 15, cn = blk & 15;
        int tok0 = b * 1024 + cn * 64;
        xbase = g_ql + (size_t)tok0 * HIDN + h * 128; ldx = HIDN;
        ybase = g_kl + (size_t)tok0 * KVD + (h >> 2) * 128; ldy = KVD;
        out = g_P + (size_t)blk * 4096;
    } else {
        int b = blk >> 6, kv = (blk >> 4) & 3, cn = blk & 15;
        int tok0 = b * 1024 + cn * 64;
        xbase = g_kl + (size_t)tok0 * KVD + kv * 128; ldx = KVD;
        ybase = xbase; ldy = KVD;
        out = g_A + (size_t)blk * 4096;
    }
    for (int i = tid * 4; i < 8192; i += 1024) {
        int r = i >> 7, c = i & 127;
        *(float4*)(Xs + i) = *(const float4*)(xbase + (size_t)r * ldx + c);
        *(float4*)(Ys + i) = *(const float4*)(ybase + (size_t)r * ldy + c);
    }
    __syncthreads();
    const int a0 = (tid >> 4) * 4, b0 = (tid & 15) * 4;
    float s4[4][4];
#pragma unroll
    for (int i = 0; i < 4; i++)
#pragma unroll
        for (int j = 0; j < 4; j++) s4[i][j] = 0.f;
    for (int d = 0; d < 128; d += 4) {
        float4 qa[4], kb[4];
#pragma unroll
        for (int i = 0; i < 4; i++) qa[i] = *(const float4*)(Xs + (a0 + i) * 128 + d);
#pragma unroll
        for (int j = 0; j < 4; j++) kb[j] = *(const float4*)(Ys + (b0 + j) * 128 + d);
#pragma unroll
        for (int i = 0; i < 4; i++)
#pragma unroll
            for (int j = 0; j < 4; j++)
                s4[i][j] += qa[i].x * kb[j].x + qa[i].y * kb[j].y + qa[i].z * kb[j].z + qa[i].w * kb[j].w;
    }
#pragma unroll
    for (int i = 0; i < 4; i++)
#pragma unroll
        for (int j = 0; j < 4; j++) {
            int t = a0 + i, s = b0 + j;
            bool keep = isP ? (s <= t) : (s < t);
            out[t * 64 + s] = keep ? s4[i][j] : 0.f;
        }
}

// ---------------- M inverse precompute (unchanged) ---------------------------
__global__ void __launch_bounds__(128) minv_kernel()
{
    extern __shared__ float ms[];
    float* As = ms;
    float* Xs = ms + 4096;
    float* bs = Xs + 8320;
    const int tid = threadIdx.x;
    const int c0 = blockIdx.x * 2, ach = blockIdx.y;
    const int b = ach >> 6, kv = (ach >> 4) & 3, cn = ach & 15;
    const int tok0 = b * 1024 + cn * 64;

    for (int i = tid * 4; i < 4096; i += 512)
        *(float4*)(As + i) = *(const float4*)(g_A + (size_t)ach * 4096 + i);
    {
        int c = tid >> 6, t = tid & 63;
        bs[c * 64 + t] = g_bt[(size_t)(tok0 + t) * KVD + kv * 128 + c0 + c];
    }
    __syncthreads();

    const int c = tid >> 6, s = tid & 63;
    float* Xc = Xs + c * 4160;
    Xc[s * 65 + s] = 1.f;
    for (int i = s + 1; i < 64; i++) {
        float acc = 0.f;
        for (int p = s; p < i; p++) acc += As[i * 64 + p] * Xc[p * 65 + s];
        Xc[i * 65 + s] = -bs[c * 64 + i] * acc;
    }
    __nv_bfloat16* dst = g_M + (size_t)((ach * 128 + c0 + c) * 64) * 64 + s;
    for (int t = 0; t < 64; t++) {
        float val = (t > s) ? Xc[t * 65 + s] : (t == s ? 1.f : 0.f);
        dst[t * 64] = __float2bfloat16(val);
    }
}

// ---------------- flash attention (unchanged) ---------------------------------
#define FQS 132
#define FKS 132
#define FVS 136
#define FSS 68

__global__ void __launch_bounds__(256) flash_kernel(
    const float* __restrict__ q, const float* __restrict__ k,
    const float* __restrict__ v, float* __restrict__ comb)
{
    extern __shared__ float fsm[];
    float* Qs = fsm;
    float* Ks = Qs + 64 * FQS;
    float* Vs = Ks + 64 * FKS;
    float* Ss = Vs + 64 * FVS;
    float* msh = Ss + 64 * FSS;
    float* lsh = msh + 64;
    float* csh = lsh + 64;
    const int tid = threadIdx.x, lane = tid & 31, warp = tid >> 5;
    const int qt = 15 - (blockIdx.x & 15);
    const int bh = blockIdx.y;
    const int b = bh >> 4, h = bh & 15, kvh = h >> 2;
    const float scale = 0.08838834764831845f;
    {
        const float* qb = q + (size_t)(b * 1024 + qt * 64) * HIDN + h * 128;
        for (int i = tid; i < 2048; i += 256) {
            int r = i >> 5, c4 = (i & 31) * 4;
            float4 t4 = *(const float4*)(qb + (size_t)r * HIDN + c4);
            Qs[r * FQS + c4 + 0] = f2tf_f(t4.x * scale);
            Qs[r * FQS + c4 + 1] = f2tf_f(t4.y * scale);
            Qs[r * FQS + c4 + 2] = f2tf_f(t4.z * scale);
            Qs[r * FQS + c4 + 3] = f2tf_f(t4.w * scale);
        }
    }
    if (tid < 64) { msh[tid] = -1e30f; lsh[tid] = 0.f; }
    const int wr2 = (warp >> 2) * 32, wc2 = (warp & 3) * 32;
    float oc[2][4][4];
#pragma unroll
    for (int mt = 0; mt < 2; mt++)
#pragma unroll
        for (int nt = 0; nt < 4; nt++)
#pragma unroll
            for (int i = 0; i < 4; i++) oc[mt][nt][i] = 0.f;

    for (int j = 0; j <= qt; j++) {
        __syncthreads();
        {
            const float* kb = k + (size_t)(b * 1024 + j * 64) * KVD + kvh * 128;
            const float* vb = v + (size_t)(b * 1024 + j * 64) * KVD + kvh * 128;
            for (int i = tid; i < 2048; i += 256) {
                int r = i >> 5, c4 = (i & 31) * 4;
                float4 k4 = *(const float4*)(kb + (size_t)r * KVD + c4);
                Ks[r * FKS + c4 + 0] = f2tf_f(k4.x); Ks[r * FKS + c4 + 1] = f2tf_f(k4.y);
                Ks[r * FKS + c4 + 2] = f2tf_f(k4.z); Ks[r * FKS + c4 + 3] = f2tf_f(k4.w);
                float4 v4 = *(const float4*)(vb + (size_t)r * KVD + c4);
                Vs[r * FVS + c4 + 0] = f2tf_f(v4.x); Vs[r * FVS + c4 + 1] = f2tf_f(v4.y);
                Vs[r * FVS + c4 + 2] = f2tf_f(v4.z); Vs[r * FVS + c4 + 3] = f2tf_f(v4.w);
            }
        }
        __syncthreads();
        {
            float sc[2][2][4];
#pragma unroll
            for (int mt = 0; mt < 2; mt++)
#pragma unroll
                for (int nt = 0; nt < 2; nt++)
#pragma unroll
                    for (int i = 0; i < 4; i++) sc[mt][nt][i] = 0.f;
            const int swr = (warp >> 2) * 32, swc = (warp & 3) * 16;
            const int r0 = swr + (lane >> 2);
#pragma unroll
            for (int ks = 0; ks < 16; ks++) {
                const int kc = ks * 8 + (lane & 3);
                unsigned a[2][4], bf[2][2];
#pragma unroll
                for (int mt = 0; mt < 2; mt++) {
                    a[mt][0] = __float_as_uint(Qs[(r0 + mt * 16) * FQS + kc]);
                    a[mt][1] = __float_as_uint(Qs[(r0 + mt * 16 + 8) * FQS + kc]);
                    a[mt][2] = __float_as_uint(Qs[(r0 + mt * 16) * FQS + kc + 4]);
                    a[mt][3] = __float_as_uint(Qs[(r0 + mt * 16 + 8) * FQS + kc + 4]);
                }
                const int nc = swc + (lane >> 2);
#pragma unroll
                for (int nt = 0; nt < 2; nt++) {
                    bf[nt][0] = __float_as_uint(Ks[(nc + nt * 8) * FKS + kc]);
                    bf[nt][1] = __float_as_uint(Ks[(nc + nt * 8) * FKS + kc + 4]);
                }
#pragma unroll
                for (int mt = 0; mt < 2; mt++)
#pragma unroll
                    for (int nt = 0; nt < 2; nt++)
                        mma8(sc[mt][nt], a[mt], bf[nt]);
            }
#pragma unroll
            for (int mt = 0; mt < 2; mt++)
#pragma unroll
                for (int nt = 0; nt < 2; nt++) {
                    int rr = swr + mt * 16 + (lane >> 2);
                    int cc = swc + nt * 8 + 2 * (lane & 3);
                    Ss[rr * FSS + cc] = sc[mt][nt][0];
                    Ss[rr * FSS + cc + 1] = sc[mt][nt][1];
                    Ss[(rr + 8) * FSS + cc] = sc[mt][nt][2];
                    Ss[(rr + 8) * FSS + cc + 1] = sc[mt][nt][3];
                }
        }
        __syncthreads();
        {
            const int row = tid >> 2, sub = tid & 3;
            float* srow = Ss + row * FSS + sub * 16;
            float pv[16];
            float mx = -1e30f;
#pragma unroll
            for (int ii = 0; ii < 16; ii++) {
                float x = srow[ii];
                if (j == qt && (sub * 16 + ii) > row) x = -1e30f;
                pv[ii] = x;
                mx = fmaxf(mx, x);
            }
            mx = fmaxf(mx, __shfl_xor_sync(~0u, mx, 1));
            mx = fmaxf(mx, __shfl_xor_sync(~0u, mx, 2));
            float mold = msh[row];
            float mnew = fmaxf(mx, mold);
            float cf = __expf(mold - mnew);
            float lsum = 0.f;
#pragma unroll
            for (int ii = 0; ii < 16; ii++) {
                float p = __expf(pv[ii] - mnew);
                srow[ii] = f2tf_f(p);
                lsum += p;
            }
            lsum += __shfl_xor_sync(~0u, lsum, 1);
            lsum += __shfl_xor_sync(~0u, lsum, 2);
            if (sub == 0) {
                msh[row] = mnew;
                lsh[row] = lsh[row] * cf + lsum;
                csh[row] = cf;
            }
        }
        __syncthreads();
        {
            const int rA = wr2 + (lane >> 2);
#pragma unroll
            for (int mt = 0; mt < 2; mt++) {
                float cl = csh[rA + mt * 16];
                float ch = csh[rA + mt * 16 + 8];
#pragma unroll
                for (int nt = 0; nt < 4; nt++) {
                    oc[mt][nt][0] *= cl; oc[mt][nt][1] *= cl;
                    oc[mt][nt][2] *= ch; oc[mt][nt][3] *= ch;
                }
            }
#pragma unroll
            for (int ks = 0; ks < 8; ks++) {
                const int kc = ks * 8 + (lane & 3);
                unsigned a[2][4], bf[4][2];
#pragma unroll
                for (int mt = 0; mt < 2; mt++) {
                    a[mt][0] = __float_as_uint(Ss[(rA + mt * 16) * FSS + kc]);
                    a[mt][1] = __float_as_uint(Ss[(rA + mt * 16 + 8) * FSS + kc]);
                    a[mt][2] = __float_as_uint(Ss[(rA + mt * 16) * FSS + kc + 4]);
                    a[mt][3] = __float_as_uint(Ss[(rA + mt * 16 + 8) * FSS + kc + 4]);
                }
                const int nc = wc2 + (lane >> 2);
#pragma unroll
                for (int nt = 0; nt < 4; nt++) {
                    bf[nt][0] = __float_as_uint(Vs[kc * FVS + nc + nt * 8]);
                    bf[nt][1] = __float_as_uint(Vs[(kc + 4) * FVS + nc + nt * 8]);
                }
#pragma unroll
                for (int mt = 0; mt < 2; mt++)
#pragma unroll
                    for (int nt = 0; nt < 4; nt++)
                        mma8(oc[mt][nt], a[mt], bf[nt]);
            }
        }
    }
#pragma unroll
    for (int mt = 0; mt < 2; mt++) {
        int r1 = wr2 + mt * 16 + (lane >> 2);
        int r2 = r1 + 8;
        float il1 = 0.5f / lsh[r1];
        float il2 = 0.5f / lsh[r2];
        size_t base1 = (size_t)(b * 1024 + qt * 64 + r1) * HIDN + h * 128;
        size_t base2 = (size_t)(b * 1024 + qt * 64 + r2) * HIDN + h * 128;
#pragma unroll
        for (int nt = 0; nt < 4; nt++) {
            int col = wc2 + nt * 8 + 2 * (lane & 3);
            *(float2*)(comb + base1 + col) = make_float2(oc[mt][nt][0] * il1, oc[mt][nt][1] * il1);
            *(float2*)(comb + base2 + col) = make_float2(oc[mt][nt][2] * il2, oc[mt][nt][3] * il2);
        }
    }
}

// ---------------- delta-rule: R12 structure + 4-way accumulator ILP ----------
#define DSTG5 10880

__device__ __forceinline__ void delta_prefetch5(float* base, int gn, int c0, int tid)
{
    int bb = gn >> 8, hh = (gn >> 4) & 15, cn = gn & 15, kv = hh >> 2;
    int tok0 = bb * 1024 + cn * 64;
    int ach = (bb * 4 + kv) * 16 + cn;
    float* K_ = base;
    __nv_bfloat16* Mb = (__nv_bfloat16*)(base + 8448);
    float* v_ = base + 10752;
    float* b_ = base + 10816;
#pragma unroll
    for (int i = 0; i < 16; i++) {
        int jj = tid + 128 * i; int tr = jj >> 5, cc = (jj & 31) << 2;
        cpa16(K_ + tr * 132 + cc, g_kl + (size_t)(tok0 + tr) * KVD + kv * 128 + cc);
    }
#pragma unroll
    for (int i = 0; i < 4; i++) {
        int jj = tid + 128 * i; int row = jj >> 3, k8 = (jj & 7) * 8;
        cpa16(Mb + row * 72 + k8,
              g_M + ((size_t)(ach * 128 + c0) * 64 + row) * 64 + k8);
    }
    if (tid < 64) {
        cpa4(v_ + tid, g_v + (size_t)(tok0 + tid) * KVD + kv * 128 + c0);
    } else {
        int tt = tid - 64;
        cpa4(b_ + tt, g_bt + (size_t)(tok0 + tt) * KVD + kv * 128 + c0);
    }
}

__global__ void __launch_bounds__(128) delta_kernel()
{
    extern __shared__ float dsm[];
    float* Ssh = dsm + 2 * DSTG5;
    float* r_ = Ssh + 128;
    float* u_ = r_ + 68;
    const int tid = threadIdx.x;
    const int c0 = blockIdx.x;
    const int t = tid >> 1, hf = tid & 1;

    float sreg = 0.f;
    Ssh[tid] = 0.f;
    delta_prefetch5(dsm, 0, c0, tid);
    CPA_COMMIT();
    __syncthreads();

    for (int gc = 0; gc < NGC; gc++) {
        if (gc + 1 < NGC) delta_prefetch5(dsm + ((gc + 1) & 1) * DSTG5, gc + 1, c0, tid);
        CPA_COMMIT();
        CPA_WAIT1();
        __syncthreads();

        float* base = dsm + (gc & 1) * DSTG5;
        float* K_ = base;
        const __nv_bfloat16* Mb = (const __nv_bfloat16*)(base + 8448);
        float* v_ = base + 10752;
        float* b_ = base + 10816;

        g_S0T[((size_t)gc * 128 + tid) * 128 + c0] = sreg;

        // phase B: 4 accumulators to break the FMA chain
        {
            float m0 = 0.f, m1 = 0.f, m2 = 0.f, m3 = 0.f;
            const float* krow = K_ + t * 132 + hf * 64;
            const float* scol = Ssh + hf * 64;
#pragma unroll
            for (int d = 0; d < 64; d += 4) {
                float4 k4 = *(const float4*)(krow + d);
                float4 s4 = *(const float4*)(scol + d);
                m0 += k4.x * s4.x; m1 += k4.y * s4.y;
                m2 += k4.z * s4.z; m3 += k4.w * s4.w;
            }
            float mm = (m0 + m1) + (m2 + m3);
            mm += __shfl_xor_sync(~0u, mm, 1);
            if (hf == 0) r_[t] = b_[t] * (v_[t] - mm);
        }
        __syncthreads();

        // u = M r: 4 accumulators
        {
            float u0 = 0.f, u1 = 0.f, u2 = 0.f, u3 = 0.f;
            const __nv_bfloat16* mrow = Mb + t * 72 + hf * 32;
            const float* rr = r_ + hf * 32;
#pragma unroll
            for (int j = 0; j < 4; j++) {
                uint4 w = *(const uint4*)(mrow + j * 8);
                float2 f0 = __bfloat1622float2(*(__nv_bfloat162*)&w.x);
                float2 f1 = __bfloat1622float2(*(__nv_bfloat162*)&w.y);
                float2 f2 = __bfloat1622float2(*(__nv_bfloat162*)&w.z);
                float2 f3 = __bfloat1622float2(*(__nv_bfloat162*)&w.w);
                float4 ra = *(const float4*)(rr + j * 8);
                float4 rb = *(const float4*)(rr + j * 8 + 4);
                u0 += f0.x * ra.x + f0.y * ra.y;
                u1 += f1.x * ra.z + f1.y * ra.w;
                u2 += f2.x * rb.x + f2.y * rb.y;
                u3 += f3.x * rb.z + f3.y * rb.w;
            }
            float u = (u0 + u1) + (u2 + u3);
            u += __shfl_xor_sync(~0u, u, 1);
            if (hf == 0) {
                u_[t] = u;
                g_U[((size_t)gc * 64 + t) * 128 + c0] = u;
            }
        }
        __syncthreads();

        // phase E: 4 accumulators
        {
            float a0 = 0.f, a1 = 0.f, a2 = 0.f, a3 = 0.f;
#pragma unroll 4
            for (int t2 = 0; t2 < 64; t2 += 4) {
                a0 += K_[(t2 + 0) * 132 + tid] * u_[t2 + 0];
                a1 += K_[(t2 + 1) * 132 + tid] * u_[t2 + 1];
                a2 += K_[(t2 + 2) * 132 + tid] * u_[t2 + 2];
                a3 += K_[(t2 + 3) * 132 + tid] * u_[t2 + 3];
            }
            sreg += (a0 + a1) + (a2 + a3);
            Ssh[tid] = sreg;
        }
        __syncthreads();
    }
}

// ---------------- okernel (unchanged from R12) --------------------------------
__global__ void __launch_bounds__(256) okernel(float* __restrict__ comb)
{
    extern __shared__ float osm[];
    float* Qs = osm;
    float* Ps = Qs + 8448;
    float* Us = Ps + 4352;
    float* S0p = Us + 8448;
    const int gc = blockIdx.x;
    const int b = gc >> 8, h = (gc >> 4) & 15, cn = gc & 15;
    const int tok0 = b * 1024 + cn * 64;
    const int tid = threadIdx.x;

    for (int i = tid; i < 2048; i += 256) {
        int r = i >> 5, c4 = (i & 31) * 4;
        *(float4*)(Qs + r * 132 + c4) =
            *(const float4*)(g_ql + (size_t)(tok0 + r) * HIDN + h * 128 + c4);
    }
    for (int i = tid; i < 1024; i += 256) {
        int r = i >> 4, c4 = (i & 15) * 4;
        *(float4*)(Ps + r * 68 + c4) = *(const float4*)(g_P + (size_t)gc * 4096 + i * 4);
    }
    for (int i = tid; i < 2048; i += 256) {
        int s = i >> 5, c4 = (i & 31) * 4;
        *(float4*)(Us + s * 132 + c4) = *(const float4*)(g_U + ((size_t)gc * 64 + s) * 128 + c4);
    }
    __syncthreads();

    const int t0 = (tid >> 4) * 4, cc0 = (tid & 15) * 8;
    float acc[4][8];
#pragma unroll
    for (int i = 0; i < 4; i++)
#pragma unroll
        for (int j = 0; j < 8; j++) acc[i][j] = 0.f;
    for (int s = 0; s < 64; s++) {
        float4 ua = *(const float4*)(Us + s * 132 + cc0);
        float4 ub = *(const float4*)(Us + s * 132 + cc0 + 4);
#pragma unroll
        for (int i = 0; i < 4; i++) {
            float p = Ps[(t0 + i) * 68 + s];
            acc[i][0] += p * ua.x; acc[i][1] += p * ua.y;
            acc[i][2] += p * ua.z; acc[i][3] += p * ua.w;
            acc[i][4] += p * ub.x; acc[i][5] += p * ub.y;
            acc[i][6] += p * ub.z; acc[i][7] += p * ub.w;
        }
    }
    for (int kp = 0; kp < 128; kp += 32) {
        __syncthreads();
        for (int i = tid; i < 1024; i += 256) {
            int k = i >> 5, c4 = (i & 31) * 4;
            *(float4*)(S0p + k * 132 + c4) =
                *(const float4*)(g_S0T + ((size_t)gc * 128 + kp + k) * 128 + c4);
        }
        __syncthreads();
        for (int k = 0; k < 32; k++) {
            float4 sa = *(const float4*)(S0p + k * 132 + cc0);
            float4 sb = *(const float4*)(S0p + k * 132 + cc0 + 4);
#pragma unroll
            for (int i = 0; i < 4; i++) {
                float qv = Qs[(t0 + i) * 132 + kp + k];
                acc[i][0] += qv * sa.x; acc[i][1] += qv * sa.y;
                acc[i][2] += qv * sa.z; acc[i][3] += qv * sa.w;
                acc[i][4] += qv * sb.x; acc[i][5] += qv * sb.y;
                acc[i][6] += qv * sb.z; acc[i][7] += qv * sb.w;
            }
        }
    }
#pragma unroll
    for (int i = 0; i < 4; i++) {
        float* dst = comb + (size_t)(tok0 + t0 + i) * HIDN + h * 128 + cc0;
        float4 o1 = *(float4*)dst;
        float4 o2 = *(float4*)(dst + 4);
        o1.x = f2tf_f(o1.x + 0.5f * acc[i][0]); o1.y = f2tf_f(o1.y + 0.5f * acc[i][1]);
        o1.z = f2tf_f(o1.z + 0.5f * acc[i][2]); o1.w = f2tf_f(o1.w + 0.5f * acc[i][3]);
        o2.x = f2tf_f(o2.x + 0.5f * acc[i][4]); o2.y = f2tf_f(o2.y + 0.5f * acc[i][5]);
        o2.z = f2tf_f(o2.z + 0.5f * acc[i][6]); o2.w = f2tf_f(o2.w + 0.5f * acc[i][7]);
        *(float4*)dst = o1; *(float4*)(dst + 4) = o2;
    }
}

// ---------------- launch -----------------------------------------------------
extern "C" void kernel_launch(void* const* d_in, const int* in_sizes, int n_in,
                              void* d_out, int out_size)
{
    const float* hs = (const float*)d_in[0];
    const float* Wq = (const float*)d_in[1];
    const float* Wk = (const float*)d_in[2];
    const float* Wv = (const float*)d_in[3];
    const float* Wo = (const float*)d_in[4];
    float* out = (float*)d_out;

    float *p_q, *p_k, *p_v, *p_comb;
    float *p_hsr, *p_wqr, *p_wkr, *p_wvr, *p_wor;
    cudaGetSymbolAddress((void**)&p_q, g_q);
    cudaGetSymbolAddress((void**)&p_k, g_k);
    cudaGetSymbolAddress((void**)&p_v, g_v);
    cudaGetSymbolAddress((void**)&p_comb, g_comb);
    cudaGetSymbolAddress((void**)&p_hsr, g_hsr);
    cudaGetSymbolAddress((void**)&p_wqr, g_wqr);
    cudaGetSymbolAddress((void**)&p_wkr, g_wkr);
    cudaGetSymbolAddress((void**)&p_wvr, g_wvr);
    cudaGetSymbolAddress((void**)&p_wor, g_wor);

    // one-time stream/event creation (host-side resources only; no device mem)
    static cudaStream_t s2 = nullptr;
    static cudaEvent_t evF = nullptr, evJ = nullptr;
    if (!s2) {
        cudaStreamCreateWithFlags(&s2, cudaStreamNonBlocking);
        cudaEventCreateWithFlags(&evF, cudaEventDisableTiming);
        cudaEventCreateWithFlags(&evJ, cudaEventDisableTiming);
    }

    const int gemm_smem = 2 * GSTG * 4;
    const int pair_smem = 8192 * 2 * 4;
    const int flash_smem = (64 * FQS + 64 * FKS + 64 * FVS + 64 * FSS + 192) * 4;
    const int delta_smem = (2 * DSTG5 + 128 + 68 + 68) * 4;
    const int minv_smem = (4096 + 8320 + 128) * 4;
    const int o_smem = (8448 + 4352 + 8448 + 32 * 132) * 4;
    cudaFuncSetAttribute(mma_gemm, cudaFuncAttributeMaxDynamicSharedMemorySize, gemm_smem);
    cudaFuncSetAttribute(pairdot_kernel, cudaFuncAttributeMaxDynamicSharedMemorySize, pair_smem);
    cudaFuncSetAttribute(flash_kernel, cudaFuncAttributeMaxDynamicSharedMemorySize, flash_smem);
    cudaFuncSetAttribute(delta_kernel, cudaFuncAttributeMaxDynamicSharedMemorySize, delta_smem);
    cudaFuncSetAttribute(minv_kernel, cudaFuncAttributeMaxDynamicSharedMemorySize, minv_smem);
    cudaFuncSetAttribute(okernel, cudaFuncAttributeMaxDynamicSharedMemorySize, o_smem);

    round_kernel<<<(TOK * HIDN / 4 + 255) / 256, 256>>>(hs, p_hsr, TOK * HIDN / 4);
    round_kernel<<<(HIDN * HIDN / 4 + 255) / 256, 256>>>(Wq, p_wqr, HIDN * HIDN / 4);
    round_kernel<<<(HIDN * KVD / 4 + 255) / 256, 256>>>(Wk, p_wkr, HIDN * KVD / 4);
    round_kernel<<<(HIDN * KVD / 4 + 255) / 256, 256>>>(Wv, p_wvr, HIDN * KVD / 4);
    round_kernel<<<(HIDN * HIDN / 4 + 255) / 256, 256>>>(Wo, p_wor, HIDN * HIDN / 4);

    mma_gemm<<<dim3(16, 16), 256, gemm_smem>>>(p_hsr, p_wqr, p_q, TOK, HIDN, HIDN);
    mma_gemm<<<dim3(4, 16), 256, gemm_smem>>>(p_hsr, p_wkr, p_k, TOK, KVD, HIDN);
    mma_gemm<<<dim3(4, 16), 256, gemm_smem>>>(p_hsr, p_wvr, p_v, TOK, KVD, HIDN);

    // fork: flash runs concurrently with the delta-preparation chain + delta
    cudaEventRecord(evF, 0);
    cudaStreamWaitEvent(s2, evF, 0);
    flash_kernel<<<dim3(16, 32), 256, flash_smem, s2>>>(p_q, p_k, p_v, p_comb);
    cudaEventRecord(evJ, s2);

    act_kernel<<<5120, 256>>>();
    pairdot_kernel<<<NACH, 256, pair_smem>>>(0);
    minv_kernel<<<dim3(64, 128), 128, minv_smem>>>();
    pairdot_kernel<<<NGC, 256, pair_smem>>>(1);
    delta_kernel<<<128, 128, delta_smem>>>();

    // join: okernel needs flash's comb writes
    cudaStreamWaitEvent(0, evJ, 0);
    okernel<<<NGC, 256, o_smem>>>(p_comb);
    mma_gemm<<<dim3(16, 16), 256, gemm_smem>>>(p_comb, p_wor, out, TOK, HIDN, HIDN);
}

// round 15
// speedup vs baseline: 1.2891x; 1.0240x over previous
#include <cuda_runtime.h>
#include <cuda_bf16.h>
#include <math.h>

#define TOK 2048
#define HIDN 2048
#define KVD 512
#define CHK 64
#define NGC 512
#define NACH 128

__device__ float g_q[TOK * HIDN];
__device__ float g_k[TOK * KVD];
__device__ float g_v[TOK * KVD];
__device__ float g_ql[TOK * HIDN];
__device__ float g_kl[TOK * KVD];
__device__ float g_bt[TOK * KVD];
__device__ float g_A[NACH * CHK * CHK];
__device__ float g_P[NGC * CHK * CHK];
__device__ float g_comb[TOK * HIDN];
__device__ __nv_bfloat16 g_M[(size_t)NACH * 128 * CHK * CHK];
__device__ float g_S0T[(size_t)NGC * 128 * 128];   // [gc][k][c]
__device__ float g_U[(size_t)NGC * CHK * 128];     // [gc][t][c]
__device__ float g_hsr[TOK * HIDN];
__device__ float g_wqr[HIDN * HIDN];
__device__ float g_wkr[HIDN * KVD];
__device__ float g_wvr[HIDN * KVD];
__device__ float g_wor[HIDN * HIDN];

__device__ __forceinline__ unsigned f2tf(float x) {
    unsigned u; asm("cvt.rna.tf32.f32 %0, %1;" : "=r"(u) : "f"(x)); return u;
}
__device__ __forceinline__ float f2tf_f(float x) { return __uint_as_float(f2tf(x)); }

__device__ __forceinline__ void mma8(float c[4], const unsigned a[4], const unsigned b[2]) {
    asm volatile(
        "mma.sync.aligned.m16n8k8.row.col.f32.tf32.tf32.f32 "
        "{%0,%1,%2,%3}, {%4,%5,%6,%7}, {%8,%9}, {%0,%1,%2,%3};"
        : "+f"(c[0]), "+f"(c[1]), "+f"(c[2]), "+f"(c[3])
        : "r"(a[0]), "r"(a[1]), "r"(a[2]), "r"(a[3]), "r"(b[0]), "r"(b[1]));
}
__device__ __forceinline__ void cpa16(void* dst, const void* src) {
    unsigned d = (unsigned)__cvta_generic_to_shared(dst);
    asm volatile("cp.async.ca.shared.global [%0], [%1], 16;" :: "r"(d), "l"(src) : "memory");
}
__device__ __forceinline__ void cpa4(void* dst, const void* src) {
    unsigned d = (unsigned)__cvta_generic_to_shared(dst);
    asm volatile("cp.async.ca.shared.global [%0], [%1], 4;" :: "r"(d), "l"(src) : "memory");
}
#define CPA_COMMIT() asm volatile("cp.async.commit_group;" ::: "memory")
#define CPA_WAIT1()  asm volatile("cp.async.wait_group 1;" ::: "memory")
#define CPA_WAIT2()  asm volatile("cp.async.wait_group 2;" ::: "memory")

// ---------------- rounding pre-pass ------------------------------------------
__global__ void __launch_bounds__(256) round_kernel(
    const float* __restrict__ src, float* __restrict__ dst, int n4)
{
    int i = blockIdx.x * 256 + threadIdx.x;
    if (i < n4) {
        float4 x = ((const float4*)src)[i];
        x.x = f2tf_f(x.x); x.y = f2tf_f(x.y);
        x.z = f2tf_f(x.z); x.w = f2tf_f(x.w);
        ((float4*)dst)[i] = x;
    }
}

// ------------------------ tf32 MMA GEMM --------------------------------------
#define GAS 36
#define GBS 136
#define GSTG (128 * GAS + 32 * GBS)

__device__ __forceinline__ void gemm_issue(
    const float* __restrict__ A, const float* __restrict__ B,
    float* As, float* Bs, int bRow, int bCol, int k0, int K, int N, int tid)
{
#pragma unroll
    for (int i = 0; i < 4; i++) {
        int lin = tid + 256 * i;
        int r = lin >> 3, c4 = (lin & 7) << 2;
        cpa16(As + r * GAS + c4, A + (size_t)(bRow + r) * K + k0 + c4);
    }
#pragma unroll
    for (int i = 0; i < 4; i++) {
        int lin = tid + 256 * i;
        int r = lin >> 5, c4 = (lin & 31) << 2;
        cpa16(Bs + r * GBS + c4, B + (size_t)(k0 + r) * N + bCol + c4);
    }
    CPA_COMMIT();
}

__global__ void __launch_bounds__(256) mma_gemm(
    const float* __restrict__ A, const float* __restrict__ B,
    float* __restrict__ C, int M, int N, int K)
{
    extern __shared__ float gsm[];
    const int tid = threadIdx.x, lane = tid & 31, warp = tid >> 5;
    const int bRow = blockIdx.y * 128, bCol = blockIdx.x * 128;
    const int wr = (warp >> 2) * 64, wc = (warp & 3) * 32;
    float acc[4][4][4];
#pragma unroll
    for (int mt = 0; mt < 4; mt++)
#pragma unroll
        for (int nt = 0; nt < 4; nt++)
#pragma unroll
            for (int i = 0; i < 4; i++) acc[mt][nt][i] = 0.f;

    gemm_issue(A, B, gsm, gsm + 128 * GAS, bRow, bCol, 0, K, N, tid);
    gemm_issue(A, B, gsm + GSTG, gsm + GSTG + 128 * GAS, bRow, bCol, 32, K, N, tid);

    const int iters = K / 32;
    for (int it = 0; it < iters; it++) {
        CPA_WAIT1();
        __syncthreads();
        float* As = gsm + (it & 1) * GSTG;
        float* Bs = As + 128 * GAS;
#pragma unroll
        for (int kk = 0; kk < 4; kk++) {
            unsigned a[4][4], bfr[4][2];
            const int kc = kk * 8 + (lane & 3);
            const int r0 = wr + (lane >> 2);
#pragma unroll
            for (int mt = 0; mt < 4; mt++) {
                a[mt][0] = __float_as_uint(As[(r0 + mt * 16) * GAS + kc]);
                a[mt][1] = __float_as_uint(As[(r0 + mt * 16 + 8) * GAS + kc]);
                a[mt][2] = __float_as_uint(As[(r0 + mt * 16) * GAS + kc + 4]);
                a[mt][3] = __float_as_uint(As[(r0 + mt * 16 + 8) * GAS + kc + 4]);
            }
            const int nc0 = wc + (lane >> 2);
#pragma unroll
            for (int nt = 0; nt < 4; nt++) {
                bfr[nt][0] = __float_as_uint(Bs[kc * GBS + nc0 + nt * 8]);
                bfr[nt][1] = __float_as_uint(Bs[(kc + 4) * GBS + nc0 + nt * 8]);
            }
#pragma unroll
            for (int mt = 0; mt < 4; mt++)
#pragma unroll
                for (int nt = 0; nt < 4; nt++)
                    mma8(acc[mt][nt], a[mt], bfr[nt]);
        }
        __syncthreads();
        if (it + 2 < iters) {
            float* As2 = gsm + (it & 1) * GSTG;
            gemm_issue(A, B, As2, As2 + 128 * GAS, bRow, bCol, (it + 2) * 32, K, N, tid);
        } else {
            CPA_COMMIT();
        }
    }
    const int r0 = bRow + wr + (lane >> 2);
    const int c0 = bCol + wc + 2 * (lane & 3);
#pragma unroll
    for (int mt = 0; mt < 4; mt++)
#pragma unroll
        for (int nt = 0; nt < 4; nt++) {
            float* p1 = C + (size_t)(r0 + mt * 16) * N + c0 + nt * 8;
            float* p2 = C + (size_t)(r0 + mt * 16 + 8) * N + c0 + nt * 8;
            *(float2*)p1 = make_float2(acc[mt][nt][0], acc[mt][nt][1]);
            *(float2*)p2 = make_float2(acc[mt][nt][2], acc[mt][nt][3]);
        }
}

// ---------------- activations (unchanged) -----------------------------------
__global__ void __launch_bounds__(256) act_kernel()
{
    int wg = (blockIdx.x * 256 + threadIdx.x) >> 5;
    int lane = threadIdx.x & 31;
    if (wg < 32768) {
        float4 x = *(const float4*)(g_q + (size_t)wg * 128 + lane * 4);
        float m = fmaxf(fmaxf(x.x, x.y), fmaxf(x.z, x.w));
#pragma unroll
        for (int o = 16; o; o >>= 1) m = fmaxf(m, __shfl_xor_sync(~0u, m, o));
        float e0 = __expf(x.x - m), e1 = __expf(x.y - m), e2 = __expf(x.z - m), e3 = __expf(x.w - m);
        float s = e0 + e1 + e2 + e3;
#pragma unroll
        for (int o = 16; o; o >>= 1) s += __shfl_xor_sync(~0u, s, o);
        float inv = 1.f / s;
        *(float4*)(g_ql + (size_t)wg * 128 + lane * 4) = make_float4(e0 * inv, e1 * inv, e2 * inv, e3 * inv);
    } else {
        int rk = wg - 32768;
        if (rk >= 8192) return;
        float4 x = *(const float4*)(g_k + (size_t)rk * 128 + lane * 4);
        float m = fmaxf(fmaxf(x.x, x.y), fmaxf(x.z, x.w));
#pragma unroll
        for (int o = 16; o; o >>= 1) m = fmaxf(m, __shfl_xor_sync(~0u, m, o));
        float e0 = __expf(x.x - m), e1 = __expf(x.y - m), e2 = __expf(x.z - m), e3 = __expf(x.w - m);
        float s = e0 + e1 + e2 + e3;
#pragma unroll
        for (int o = 16; o; o >>= 1) s += __shfl_xor_sync(~0u, s, o);
        float inv = 1.f / s;
        *(float4*)(g_kl + (size_t)rk * 128 + lane * 4) = make_float4(e0 * inv, e1 * inv, e2 * inv, e3 * inv);
        float4 bt;
        bt.x = (fminf(x.x, 0.f) - log1pf(__expf(-fabsf(x.x)))) * 0.0625f;
        bt.y = (fminf(x.y, 0.f) - log1pf(__expf(-fabsf(x.y)))) * 0.0625f;
        bt.z = (fminf(x.z, 0.f) - log1pf(__expf(-fabsf(x.z)))) * 0.0625f;
        bt.w = (fminf(x.w, 0.f) - log1pf(__expf(-fabsf(x.w)))) * 0.0625f;
        *(float4*)(g_bt + (size_t)rk * 128 + lane * 4) = bt;
    }
}

// ---------------- pairwise-dot (unchanged) ----------------------------------
__global__ void __launch_bounds__(256) pairdot_kernel(int isP)
{
    extern __shared__ float sm[];
    float* Xs = sm;
    float* Ys = sm + 8192;
    const int blk = blockIdx.x;
    const int tid = threadIdx.x;
    const float* xbase; const float* ybase; float* out; int ldx, ldy;
    if (isP) {
        int b = blk >> 8, h = (blk >> 4) & 15, cn = blk & 15;
        int tok0 = b * 1024 + cn * 64;
        xbase = g_ql + (size_t)tok0 * HIDN + h * 128; ldx = HIDN;
        ybase = g_kl + (size_t)tok0 * KVD + (h >> 2) * 128; ldy = KVD;
        out = g_P + (size_t)blk * 4096;
    } else {
        int b = blk >> 6, kv = (blk >> 4) & 3, cn = blk & 15;
        int tok0 = b * 1024 + cn * 64;
        xbase = g_kl + (size_t)tok0 * KVD + kv * 128; ldx = KVD;
        ybase = xbase; ldy = KVD;
        out = g_A + (size_t)blk * 4096;
    }
    for (int i = tid * 4; i < 8192; i += 1024) {
        int r = i >> 7, c = i & 127;
        *(float4*)(Xs + i) = *(const float4*)(xbase + (size_t)r * ldx + c);
        *(float4*)(Ys + i) = *(const float4*)(ybase + (size_t)r * ldy + c);
    }
    __syncthreads();
    const int a0 = (tid >> 4) * 4, b0 = (tid & 15) * 4;
    float s4[4][4];
#pragma unroll
    for (int i = 0; i < 4; i++)
#pragma unroll
        for (int j = 0; j < 4; j++) s4[i][j] = 0.f;
    for (int d = 0; d < 128; d += 4) {
        float4 qa[4], kb[4];
#pragma unroll
        for (int i = 0; i < 4; i++) qa[i] = *(const float4*)(Xs + (a0 + i) * 128 + d);
#pragma unroll
        for (int j = 0; j < 4; j++) kb[j] = *(const float4*)(Ys + (b0 + j) * 128 + d);
#pragma unroll
        for (int i = 0; i < 4; i++)
#pragma unroll
            for (int j = 0; j < 4; j++)
                s4[i][j] += qa[i].x * kb[j].x + qa[i].y * kb[j].y + qa[i].z * kb[j].z + qa[i].w * kb[j].w;
    }
#pragma unroll
    for (int i = 0; i < 4; i++)
#pragma unroll
        for (int j = 0; j < 4; j++) {
            int t = a0 + i, s = b0 + j;
            bool keep = isP ? (s <= t) : (s < t);
            out[t * 64 + s] = keep ? s4[i][j] : 0.f;
        }
}

// ---------------- M inverse precompute (unchanged) ---------------------------
__global__ void __launch_bounds__(128) minv_kernel()
{
    extern __shared__ float ms[];
    float* As = ms;
    float* Xs = ms + 4096;
    float* bs = Xs + 8320;
    const int tid = threadIdx.x;
    const int c0 = blockIdx.x * 2, ach = blockIdx.y;
    const int b = ach >> 6, kv = (ach >> 4) & 3, cn = ach & 15;
    const int tok0 = b * 1024 + cn * 64;

    for (int i = tid * 4; i < 4096; i += 512)
        *(float4*)(As + i) = *(const float4*)(g_A + (size_t)ach * 4096 + i);
    {
        int c = tid >> 6, t = tid & 63;
        bs[c * 64 + t] = g_bt[(size_t)(tok0 + t) * KVD + kv * 128 + c0 + c];
    }
    __syncthreads();

    const int c = tid >> 6, s = tid & 63;
    float* Xc = Xs + c * 4160;
    Xc[s * 65 + s] = 1.f;
    for (int i = s + 1; i < 64; i++) {
        float acc = 0.f;
        for (int p = s; p < i; p++) acc += As[i * 64 + p] * Xc[p * 65 + s];
        Xc[i * 65 + s] = -bs[c * 64 + i] * acc;
    }
    __nv_bfloat16* dst = g_M + (size_t)((ach * 128 + c0 + c) * 64) * 64 + s;
    for (int t = 0; t < 64; t++) {
        float val = (t > s) ? Xc[t * 65 + s] : (t == s ? 1.f : 0.f);
        dst[t * 64] = __float2bfloat16(val);
    }
}

// ---------------- flash attention (unchanged) ---------------------------------
#define FQS 132
#define FKS 132
#define FVS 136
#define FSS 68

__global__ void __launch_bounds__(256) flash_kernel(
    const float* __restrict__ q, const float* __restrict__ k,
    const float* __restrict__ v, float* __restrict__ comb)
{
    extern __shared__ float fsm[];
    float* Qs = fsm;
    float* Ks = Qs + 64 * FQS;
    float* Vs = Ks + 64 * FKS;
    float* Ss = Vs + 64 * FVS;
    float* msh = Ss + 64 * FSS;
    float* lsh = msh + 64;
    float* csh = lsh + 64;
    const int tid = threadIdx.x, lane = tid & 31, warp = tid >> 5;
    const int qt = 15 - (blockIdx.x & 15);
    const int bh = blockIdx.y;
    const int b = bh >> 4, h = bh & 15, kvh = h >> 2;
    const float scale = 0.08838834764831845f;
    {
        const float* qb = q + (size_t)(b * 1024 + qt * 64) * HIDN + h * 128;
        for (int i = tid; i < 2048; i += 256) {
            int r = i >> 5, c4 = (i & 31) * 4;
            float4 t4 = *(const float4*)(qb + (size_t)r * HIDN + c4);
            Qs[r * FQS + c4 + 0] = f2tf_f(t4.x * scale);
            Qs[r * FQS + c4 + 1] = f2tf_f(t4.y * scale);
            Qs[r * FQS + c4 + 2] = f2tf_f(t4.z * scale);
            Qs[r * FQS + c4 + 3] = f2tf_f(t4.w * scale);
        }
    }
    if (tid < 64) { msh[tid] = -1e30f; lsh[tid] = 0.f; }
    const int wr2 = (warp >> 2) * 32, wc2 = (warp & 3) * 32;
    float oc[2][4][4];
#pragma unroll
    for (int mt = 0; mt < 2; mt++)
#pragma unroll
        for (int nt = 0; nt < 4; nt++)
#pragma unroll
            for (int i = 0; i < 4; i++) oc[mt][nt][i] = 0.f;

    for (int j = 0; j <= qt; j++) {
        __syncthreads();
        {
            const float* kb = k + (size_t)(b * 1024 + j * 64) * KVD + kvh * 128;
            const float* vb = v + (size_t)(b * 1024 + j * 64) * KVD + kvh * 128;
            for (int i = tid; i < 2048; i += 256) {
                int r = i >> 5, c4 = (i & 31) * 4;
                float4 k4 = *(const float4*)(kb + (size_t)r * KVD + c4);
                Ks[r * FKS + c4 + 0] = f2tf_f(k4.x); Ks[r * FKS + c4 + 1] = f2tf_f(k4.y);
                Ks[r * FKS + c4 + 2] = f2tf_f(k4.z); Ks[r * FKS + c4 + 3] = f2tf_f(k4.w);
                float4 v4 = *(const float4*)(vb + (size_t)r * KVD + c4);
                Vs[r * FVS + c4 + 0] = f2tf_f(v4.x); Vs[r * FVS + c4 + 1] = f2tf_f(v4.y);
                Vs[r * FVS + c4 + 2] = f2tf_f(v4.z); Vs[r * FVS + c4 + 3] = f2tf_f(v4.w);
            }
        }
        __syncthreads();
        {
            float sc[2][2][4];
#pragma unroll
            for (int mt = 0; mt < 2; mt++)
#pragma unroll
                for (int nt = 0; nt < 2; nt++)
#pragma unroll
                    for (int i = 0; i < 4; i++) sc[mt][nt][i] = 0.f;
            const int swr = (warp >> 2) * 32, swc = (warp & 3) * 16;
            const int r0 = swr + (lane >> 2);
#pragma unroll
            for (int ks = 0; ks < 16; ks++) {
                const int kc = ks * 8 + (lane & 3);
                unsigned a[2][4], bf[2][2];
#pragma unroll
                for (int mt = 0; mt < 2; mt++) {
                    a[mt][0] = __float_as_uint(Qs[(r0 + mt * 16) * FQS + kc]);
                    a[mt][1] = __float_as_uint(Qs[(r0 + mt * 16 + 8) * FQS + kc]);
                    a[mt][2] = __float_as_uint(Qs[(r0 + mt * 16) * FQS + kc + 4]);
                    a[mt][3] = __float_as_uint(Qs[(r0 + mt * 16 + 8) * FQS + kc + 4]);
                }
                const int nc = swc + (lane >> 2);
#pragma unroll
                for (int nt = 0; nt < 2; nt++) {
                    bf[nt][0] = __float_as_uint(Ks[(nc + nt * 8) * FKS + kc]);
                    bf[nt][1] = __float_as_uint(Ks[(nc + nt * 8) * FKS + kc + 4]);
                }
#pragma unroll
                for (int mt = 0; mt < 2; mt++)
#pragma unroll
                    for (int nt = 0; nt < 2; nt++)
                        mma8(sc[mt][nt], a[mt], bf[nt]);
            }
#pragma unroll
            for (int mt = 0; mt < 2; mt++)
#pragma unroll
                for (int nt = 0; nt < 2; nt++) {
                    int rr = swr + mt * 16 + (lane >> 2);
                    int cc = swc + nt * 8 + 2 * (lane & 3);
                    Ss[rr * FSS + cc] = sc[mt][nt][0];
                    Ss[rr * FSS + cc + 1] = sc[mt][nt][1];
                    Ss[(rr + 8) * FSS + cc] = sc[mt][nt][2];
                    Ss[(rr + 8) * FSS + cc + 1] = sc[mt][nt][3];
                }
        }
        __syncthreads();
        {
            const int row = tid >> 2, sub = tid & 3;
            float* srow = Ss + row * FSS + sub * 16;
            float pv[16];
            float mx = -1e30f;
#pragma unroll
            for (int ii = 0; ii < 16; ii++) {
                float x = srow[ii];
                if (j == qt && (sub * 16 + ii) > row) x = -1e30f;
                pv[ii] = x;
                mx = fmaxf(mx, x);
            }
            mx = fmaxf(mx, __shfl_xor_sync(~0u, mx, 1));
            mx = fmaxf(mx, __shfl_xor_sync(~0u, mx, 2));
            float mold = msh[row];
            float mnew = fmaxf(mx, mold);
            float cf = __expf(mold - mnew);
            float lsum = 0.f;
#pragma unroll
            for (int ii = 0; ii < 16; ii++) {
                float p = __expf(pv[ii] - mnew);
                srow[ii] = f2tf_f(p);
                lsum += p;
            }
            lsum += __shfl_xor_sync(~0u, lsum, 1);
            lsum += __shfl_xor_sync(~0u, lsum, 2);
            if (sub == 0) {
                msh[row] = mnew;
                lsh[row] = lsh[row] * cf + lsum;
                csh[row] = cf;
            }
        }
        __syncthreads();
        {
            const int rA = wr2 + (lane >> 2);
#pragma unroll
            for (int mt = 0; mt < 2; mt++) {
                float cl = csh[rA + mt * 16];
                float ch = csh[rA + mt * 16 + 8];
#pragma unroll
                for (int nt = 0; nt < 4; nt++) {
                    oc[mt][nt][0] *= cl; oc[mt][nt][1] *= cl;
                    oc[mt][nt][2] *= ch; oc[mt][nt][3] *= ch;
                }
            }
#pragma unroll
            for (int ks = 0; ks < 8; ks++) {
                const int kc = ks * 8 + (lane & 3);
                unsigned a[2][4], bf[4][2];
#pragma unroll
                for (int mt = 0; mt < 2; mt++) {
                    a[mt][0] = __float_as_uint(Ss[(rA + mt * 16) * FSS + kc]);
                    a[mt][1] = __float_as_uint(Ss[(rA + mt * 16 + 8) * FSS + kc]);
                    a[mt][2] = __float_as_uint(Ss[(rA + mt * 16) * FSS + kc + 4]);
                    a[mt][3] = __float_as_uint(Ss[(rA + mt * 16 + 8) * FSS + kc + 4]);
                }
                const int nc = wc2 + (lane >> 2);
#pragma unroll
                for (int nt = 0; nt < 4; nt++) {
                    bf[nt][0] = __float_as_uint(Vs[kc * FVS + nc + nt * 8]);
                    bf[nt][1] = __float_as_uint(Vs[(kc + 4) * FVS + nc + nt * 8]);
                }
#pragma unroll
                for (int mt = 0; mt < 2; mt++)
#pragma unroll
                    for (int nt = 0; nt < 4; nt++)
                        mma8(oc[mt][nt], a[mt], bf[nt]);
            }
        }
    }
#pragma unroll
    for (int mt = 0; mt < 2; mt++) {
        int r1 = wr2 + mt * 16 + (lane >> 2);
        int r2 = r1 + 8;
        float il1 = 0.5f / lsh[r1];
        float il2 = 0.5f / lsh[r2];
        size_t base1 = (size_t)(b * 1024 + qt * 64 + r1) * HIDN + h * 128;
        size_t base2 = (size_t)(b * 1024 + qt * 64 + r2) * HIDN + h * 128;
#pragma unroll
        for (int nt = 0; nt < 4; nt++) {
            int col = wc2 + nt * 8 + 2 * (lane & 3);
            *(float2*)(comb + base1 + col) = make_float2(oc[mt][nt][0] * il1, oc[mt][nt][1] * il1);
            *(float2*)(comb + base2 + col) = make_float2(oc[mt][nt][2] * il2, oc[mt][nt][3] * il2);
        }
    }
}

// ---------------- delta-rule: triple-buffered, 3 barriers/chunk --------------
#define DSTG5 10880

__device__ __forceinline__ void delta_prefetch5(float* base, int gn, int c0, int tid)
{
    int bb = gn >> 8, hh = (gn >> 4) & 15, cn = gn & 15, kv = hh >> 2;
    int tok0 = bb * 1024 + cn * 64;
    int ach = (bb * 4 + kv) * 16 + cn;
    float* K_ = base;
    __nv_bfloat16* Mb = (__nv_bfloat16*)(base + 8448);
    float* v_ = base + 10752;
    float* b_ = base + 10816;
#pragma unroll
    for (int i = 0; i < 16; i++) {
        int jj = tid + 128 * i; int tr = jj >> 5, cc = (jj & 31) << 2;
        cpa16(K_ + tr * 132 + cc, g_kl + (size_t)(tok0 + tr) * KVD + kv * 128 + cc);
    }
#pragma unroll
    for (int i = 0; i < 4; i++) {
        int jj = tid + 128 * i; int row = jj >> 3, k8 = (jj & 7) * 8;
        cpa16(Mb + row * 72 + k8,
              g_M + ((size_t)(ach * 128 + c0) * 64 + row) * 64 + k8);
    }
    if (tid < 64) {
        cpa4(v_ + tid, g_v + (size_t)(tok0 + tid) * KVD + kv * 128 + c0);
    } else {
        int tt = tid - 64;
        cpa4(b_ + tt, g_bt + (size_t)(tok0 + tt) * KVD + kv * 128 + c0);
    }
}

__global__ void __launch_bounds__(128) delta_kernel()
{
    extern __shared__ float dsm[];
    float* Ssh = dsm + 3 * DSTG5;
    float* r_ = Ssh + 128;
    float* u_ = r_ + 68;
    const int tid = threadIdx.x;
    const int c0 = blockIdx.x;
    const int t = tid >> 1, hf = tid & 1;

    float sreg = 0.f;
    Ssh[tid] = 0.f;
    delta_prefetch5(dsm, 0, c0, tid);
    CPA_COMMIT();
    delta_prefetch5(dsm + DSTG5, 1, c0, tid);
    CPA_COMMIT();

    for (int gc = 0; gc < NGC; gc++) {
        if (gc + 2 < NGC)
            delta_prefetch5(dsm + ((gc + 2) % 3) * DSTG5, gc + 2, c0, tid);
        CPA_COMMIT();
        CPA_WAIT2();
        __syncthreads();   // also orders prev phase E's Ssh/u_ writes

        float* base = dsm + (gc % 3) * DSTG5;
        float* K_ = base;
        const __nv_bfloat16* Mb = (const __nv_bfloat16*)(base + 8448);
        float* v_ = base + 10752;
        float* b_ = base + 10816;

        g_S0T[((size_t)gc * 128 + tid) * 128 + c0] = sreg;

        // phase B: 4 accumulators
        {
            float m0 = 0.f, m1 = 0.f, m2 = 0.f, m3 = 0.f;
            const float* krow = K_ + t * 132 + hf * 64;
            const float* scol = Ssh + hf * 64;
#pragma unroll
            for (int d = 0; d < 64; d += 4) {
                float4 k4 = *(const float4*)(krow + d);
                float4 s4 = *(const float4*)(scol + d);
                m0 += k4.x * s4.x; m1 += k4.y * s4.y;
                m2 += k4.z * s4.z; m3 += k4.w * s4.w;
            }
            float mm = (m0 + m1) + (m2 + m3);
            mm += __shfl_xor_sync(~0u, mm, 1);
            if (hf == 0) r_[t] = b_[t] * (v_[t] - mm);
        }
        __syncthreads();

        // u = M r: 4 accumulators
        {
            float u0 = 0.f, u1 = 0.f, u2 = 0.f, u3 = 0.f;
            const __nv_bfloat16* mrow = Mb + t * 72 + hf * 32;
            const float* rr = r_ + hf * 32;
#pragma unroll
            for (int j = 0; j < 4; j++) {
                uint4 w = *(const uint4*)(mrow + j * 8);
                float2 f0 = __bfloat1622float2(*(__nv_bfloat162*)&w.x);
                float2 f1 = __bfloat1622float2(*(__nv_bfloat162*)&w.y);
                float2 f2 = __bfloat1622float2(*(__nv_bfloat162*)&w.z);
                float2 f3 = __bfloat1622float2(*(__nv_bfloat162*)&w.w);
                float4 ra = *(const float4*)(rr + j * 8);
                float4 rb = *(const float4*)(rr + j * 8 + 4);
                u0 += f0.x * ra.x + f0.y * ra.y;
                u1 += f1.x * ra.z + f1.y * ra.w;
                u2 += f2.x * rb.x + f2.y * rb.y;
                u3 += f3.x * rb.z + f3.y * rb.w;
            }
            float u = (u0 + u1) + (u2 + u3);
            u += __shfl_xor_sync(~0u, u, 1);
            if (hf == 0) {
                u_[t] = u;
                g_U[((size_t)gc * 64 + t) * 128 + c0] = u;
            }
        }
        __syncthreads();

        // phase E: 4 accumulators (no trailing barrier — top barrier covers it)
        {
            float a0 = 0.f, a1 = 0.f, a2 = 0.f, a3 = 0.f;
#pragma unroll 4
            for (int t2 = 0; t2 < 64; t2 += 4) {
                a0 += K_[(t2 + 0) * 132 + tid] * u_[t2 + 0];
                a1 += K_[(t2 + 1) * 132 + tid] * u_[t2 + 1];
                a2 += K_[(t2 + 2) * 132 + tid] * u_[t2 + 2];
                a3 += K_[(t2 + 3) * 132 + tid] * u_[t2 + 3];
            }
            sreg += (a0 + a1) + (a2 + a3);
            Ssh[tid] = sreg;
        }
    }
}

// ---------------- okernel (unchanged) -----------------------------------------
__global__ void __launch_bounds__(256) okernel(float* __restrict__ comb)
{
    extern __shared__ float osm[];
    float* Qs = osm;
    float* Ps = Qs + 8448;
    float* Us = Ps + 4352;
    float* S0p = Us + 8448;
    const int gc = blockIdx.x;
    const int b = gc >> 8, h = (gc >> 4) & 15, cn = gc & 15;
    const int tok0 = b * 1024 + cn * 64;
    const int tid = threadIdx.x;

    for (int i = tid; i < 2048; i += 256) {
        int r = i >> 5, c4 = (i & 31) * 4;
        *(float4*)(Qs + r * 132 + c4) =
            *(const float4*)(g_ql + (size_t)(tok0 + r) * HIDN + h * 128 + c4);
    }
    for (int i = tid; i < 1024; i += 256) {
        int r = i >> 4, c4 = (i & 15) * 4;
        *(float4*)(Ps + r * 68 + c4) = *(const float4*)(g_P + (size_t)gc * 4096 + i * 4);
    }
    for (int i = tid; i < 2048; i += 256) {
        int s = i >> 5, c4 = (i & 31) * 4;
        *(float4*)(Us + s * 132 + c4) = *(const float4*)(g_U + ((size_t)gc * 64 + s) * 128 + c4);
    }
    __syncthreads();

    const int t0 = (tid >> 4) * 4, cc0 = (tid & 15) * 8;
    float acc[4][8];
#pragma unroll
    for (int i = 0; i < 4; i++)
#pragma unroll
        for (int j = 0; j < 8; j++) acc[i][j] = 0.f;
    for (int s = 0; s < 64; s++) {
        float4 ua = *(const float4*)(Us + s * 132 + cc0);
        float4 ub = *(const float4*)(Us + s * 132 + cc0 + 4);
#pragma unroll
        for (int i = 0; i < 4; i++) {
            float p = Ps[(t0 + i) * 68 + s];
            acc[i][0] += p * ua.x; acc[i][1] += p * ua.y;
            acc[i][2] += p * ua.z; acc[i][3] += p * ua.w;
            acc[i][4] += p * ub.x; acc[i][5] += p * ub.y;
            acc[i][6] += p * ub.z; acc[i][7] += p * ub.w;
        }
    }
    for (int kp = 0; kp < 128; kp += 32) {
        __syncthreads();
        for (int i = tid; i < 1024; i += 256) {
            int k = i >> 5, c4 = (i & 31) * 4;
            *(float4*)(S0p + k * 132 + c4) =
                *(const float4*)(g_S0T + ((size_t)gc * 128 + kp + k) * 128 + c4);
        }
        __syncthreads();
        for (int k = 0; k < 32; k++) {
            float4 sa = *(const float4*)(S0p + k * 132 + cc0);
            float4 sb = *(const float4*)(S0p + k * 132 + cc0 + 4);
#pragma unroll
            for (int i = 0; i < 4; i++) {
                float qv = Qs[(t0 + i) * 132 + kp + k];
                acc[i][0] += qv * sa.x; acc[i][1] += qv * sa.y;
                acc[i][2] += qv * sa.z; acc[i][3] += qv * sa.w;
                acc[i][4] += qv * sb.x; acc[i][5] += qv * sb.y;
                acc[i][6] += qv * sb.z; acc[i][7] += qv * sb.w;
            }
        }
    }
#pragma unroll
    for (int i = 0; i < 4; i++) {
        float* dst = comb + (size_t)(tok0 + t0 + i) * HIDN + h * 128 + cc0;
        float4 o1 = *(float4*)dst;
        float4 o2 = *(float4*)(dst + 4);
        o1.x = f2tf_f(o1.x + 0.5f * acc[i][0]); o1.y = f2tf_f(o1.y + 0.5f * acc[i][1]);
        o1.z = f2tf_f(o1.z + 0.5f * acc[i][2]); o1.w = f2tf_f(o1.w + 0.5f * acc[i][3]);
        o2.x = f2tf_f(o2.x + 0.5f * acc[i][4]); o2.y = f2tf_f(o2.y + 0.5f * acc[i][5]);
        o2.z = f2tf_f(o2.z + 0.5f * acc[i][6]); o2.w = f2tf_f(o2.w + 0.5f * acc[i][7]);
        *(float4*)dst = o1; *(float4*)(dst + 4) = o2;
    }
}

// ---------------- launch -----------------------------------------------------
extern "C" void kernel_launch(void* const* d_in, const int* in_sizes, int n_in,
                              void* d_out, int out_size)
{
    const float* hs = (const float*)d_in[0];
    const float* Wq = (const float*)d_in[1];
    const float* Wk = (const float*)d_in[2];
    const float* Wv = (const float*)d_in[3];
    const float* Wo = (const float*)d_in[4];
    float* out = (float*)d_out;

    float *p_q, *p_k, *p_v, *p_comb;
    float *p_hsr, *p_wqr, *p_wkr, *p_wvr, *p_wor;
    cudaGetSymbolAddress((void**)&p_q, g_q);
    cudaGetSymbolAddress((void**)&p_k, g_k);
    cudaGetSymbolAddress((void**)&p_v, g_v);
    cudaGetSymbolAddress((void**)&p_comb, g_comb);
    cudaGetSymbolAddress((void**)&p_hsr, g_hsr);
    cudaGetSymbolAddress((void**)&p_wqr, g_wqr);
    cudaGetSymbolAddress((void**)&p_wkr, g_wkr);
    cudaGetSymbolAddress((void**)&p_wvr, g_wvr);
    cudaGetSymbolAddress((void**)&p_wor, g_wor);

    static cudaStream_t s2 = nullptr;
    static cudaEvent_t evF = nullptr, evA = nullptr, evJ = nullptr;
    if (!s2) {
        cudaStreamCreateWithFlags(&s2, cudaStreamNonBlocking);
        cudaEventCreateWithFlags(&evF, cudaEventDisableTiming);
        cudaEventCreateWithFlags(&evA, cudaEventDisableTiming);
        cudaEventCreateWithFlags(&evJ, cudaEventDisableTiming);
    }

    const int gemm_smem = 2 * GSTG * 4;
    const int pair_smem = 8192 * 2 * 4;
    const int flash_smem = (64 * FQS + 64 * FKS + 64 * FVS + 64 * FSS + 192) * 4;
    const int delta_smem = (3 * DSTG5 + 128 + 68 + 68) * 4;
    const int minv_smem = (4096 + 8320 + 128) * 4;
    const int o_smem = (8448 + 4352 + 8448 + 32 * 132) * 4;
    cudaFuncSetAttribute(mma_gemm, cudaFuncAttributeMaxDynamicSharedMemorySize, gemm_smem);
    cudaFuncSetAttribute(pairdot_kernel, cudaFuncAttributeMaxDynamicSharedMemorySize, pair_smem);
    cudaFuncSetAttribute(flash_kernel, cudaFuncAttributeMaxDynamicSharedMemorySize, flash_smem);
    cudaFuncSetAttribute(delta_kernel, cudaFuncAttributeMaxDynamicSharedMemorySize, delta_smem);
    cudaFuncSetAttribute(minv_kernel, cudaFuncAttributeMaxDynamicSharedMemorySize, minv_smem);
    cudaFuncSetAttribute(okernel, cudaFuncAttributeMaxDynamicSharedMemorySize, o_smem);

    round_kernel<<<(TOK * HIDN / 4 + 255) / 256, 256>>>(hs, p_hsr, TOK * HIDN / 4);
    round_kernel<<<(HIDN * HIDN / 4 + 255) / 256, 256>>>(Wq, p_wqr, HIDN * HIDN / 4);
    round_kernel<<<(HIDN * KVD / 4 + 255) / 256, 256>>>(Wk, p_wkr, HIDN * KVD / 4);
    round_kernel<<<(HIDN * KVD / 4 + 255) / 256, 256>>>(Wv, p_wvr, HIDN * KVD / 4);
    round_kernel<<<(HIDN * HIDN / 4 + 255) / 256, 256>>>(Wo, p_wor, HIDN * HIDN / 4);

    mma_gemm<<<dim3(16, 16), 256, gemm_smem>>>(p_hsr, p_wqr, p_q, TOK, HIDN, HIDN);
    mma_gemm<<<dim3(4, 16), 256, gemm_smem>>>(p_hsr, p_wkr, p_k, TOK, KVD, HIDN);
    mma_gemm<<<dim3(4, 16), 256, gemm_smem>>>(p_hsr, p_wvr, p_v, TOK, KVD, HIDN);

    // fork: flash (needs only gemms) on s2
    cudaEventRecord(evF, 0);
    cudaStreamWaitEvent(s2, evF, 0);
    flash_kernel<<<dim3(16, 32), 256, flash_smem, s2>>>(p_q, p_k, p_v, p_comb);

    // critical chain on default stream
    act_kernel<<<5120, 256>>>();
    cudaEventRecord(evA, 0);

    // pairdotP off the critical path (needs act) — runs on s2 after flash
    cudaStreamWaitEvent(s2, evA, 0);
    pairdot_kernel<<<NGC, 256, pair_smem, s2>>>(1);
    cudaEventRecord(evJ, s2);

    pairdot_kernel<<<NACH, 256, pair_smem>>>(0);
    minv_kernel<<<dim3(64, 128), 128, minv_smem>>>();
    delta_kernel<<<128, 128, delta_smem>>>();

    // join: okernel needs flash's comb + pairdotP's g_P
    cudaStreamWaitEvent(0, evJ, 0);
    okernel<<<NGC, 256, o_smem>>>(p_comb);
    mma_gemm<<<dim3(16, 16), 256, gemm_smem>>>(p_comb, p_wor, out, TOK, HIDN, HIDN);
}

// round 16
// speedup vs baseline: 1.3296x; 1.0314x over previous
#include <cuda_runtime.h>
#include <cuda_bf16.h>
#include <math.h>

#define TOK 2048
#define HIDN 2048
#define KVD 512
#define CHK 64
#define NGC 512
#define NACH 128

__device__ float g_q[TOK * HIDN];
__device__ float g_k[TOK * KVD];
__device__ float g_v[TOK * KVD];
__device__ float g_ql[TOK * HIDN];
__device__ float g_kl[TOK * KVD];
__device__ float g_bt[TOK * KVD];
__device__ float g_A[NACH * CHK * CHK];
__device__ float g_P[NGC * CHK * CHK];
__device__ float g_comb[TOK * HIDN];
__device__ __nv_bfloat16 g_M[(size_t)NACH * 128 * CHK * CHK];
__device__ float g_S0T[(size_t)NGC * 128 * 128];
__device__ float g_U[(size_t)NGC * CHK * 128];
__device__ float g_hsr[TOK * HIDN];
__device__ float g_wqr[HIDN * HIDN];
__device__ float g_wkr[HIDN * KVD];
__device__ float g_wvr[HIDN * KVD];
__device__ float g_wor[HIDN * HIDN];

__device__ __forceinline__ unsigned f2tf(float x) {
    unsigned u; asm("cvt.rna.tf32.f32 %0, %1;" : "=r"(u) : "f"(x)); return u;
}
__device__ __forceinline__ float f2tf_f(float x) { return __uint_as_float(f2tf(x)); }

__device__ __forceinline__ void mma8(float c[4], const unsigned a[4], const unsigned b[2]) {
    asm volatile(
        "mma.sync.aligned.m16n8k8.row.col.f32.tf32.tf32.f32 "
        "{%0,%1,%2,%3}, {%4,%5,%6,%7}, {%8,%9}, {%0,%1,%2,%3};"
        : "+f"(c[0]), "+f"(c[1]), "+f"(c[2]), "+f"(c[3])
        : "r"(a[0]), "r"(a[1]), "r"(a[2]), "r"(a[3]), "r"(b[0]), "r"(b[1]));
}
__device__ __forceinline__ void cpa16(void* dst, const void* src) {
    unsigned d = (unsigned)__cvta_generic_to_shared(dst);
    asm volatile("cp.async.ca.shared.global [%0], [%1], 16;" :: "r"(d), "l"(src) : "memory");
}
__device__ __forceinline__ void cpa4(void* dst, const void* src) {
    unsigned d = (unsigned)__cvta_generic_to_shared(dst);
    asm volatile("cp.async.ca.shared.global [%0], [%1], 4;" :: "r"(d), "l"(src) : "memory");
}
#define CPA_COMMIT() asm volatile("cp.async.commit_group;" ::: "memory")
#define CPA_WAIT1()  asm volatile("cp.async.wait_group 1;" ::: "memory")
#define CPA_WAIT2()  asm volatile("cp.async.wait_group 2;" ::: "memory")

// ---------------- rounding pre-pass ------------------------------------------
__global__ void __launch_bounds__(256) round_kernel(
    const float* __restrict__ src, float* __restrict__ dst, int n4)
{
    int i = blockIdx.x * 256 + threadIdx.x;
    if (i < n4) {
        float4 x = ((const float4*)src)[i];
        x.x = f2tf_f(x.x); x.y = f2tf_f(x.y);
        x.z = f2tf_f(x.z); x.w = f2tf_f(x.w);
        ((float4*)dst)[i] = x;
    }
}

// ------------------------ tf32 MMA GEMM --------------------------------------
#define GAS 36
#define GBS 136
#define GSTG (128 * GAS + 32 * GBS)

__device__ __forceinline__ void gemm_issue(
    const float* __restrict__ A, const float* __restrict__ B,
    float* As, float* Bs, int bRow, int bCol, int k0, int K, int N, int tid)
{
#pragma unroll
    for (int i = 0; i < 4; i++) {
        int lin = tid + 256 * i;
        int r = lin >> 3, c4 = (lin & 7) << 2;
        cpa16(As + r * GAS + c4, A + (size_t)(bRow + r) * K + k0 + c4);
    }
#pragma unroll
    for (int i = 0; i < 4; i++) {
        int lin = tid + 256 * i;
        int r = lin >> 5, c4 = (lin & 31) << 2;
        cpa16(Bs + r * GBS + c4, B + (size_t)(k0 + r) * N + bCol + c4);
    }
    CPA_COMMIT();
}

__global__ void __launch_bounds__(256) mma_gemm(
    const float* __restrict__ A, const float* __restrict__ B,
    float* __restrict__ C, int M, int N, int K)
{
    extern __shared__ float gsm[];
    const int tid = threadIdx.x, lane = tid & 31, warp = tid >> 5;
    const int bRow = blockIdx.y * 128, bCol = blockIdx.x * 128;
    const int wr = (warp >> 2) * 64, wc = (warp & 3) * 32;
    float acc[4][4][4];
#pragma unroll
    for (int mt = 0; mt < 4; mt++)
#pragma unroll
        for (int nt = 0; nt < 4; nt++)
#pragma unroll
            for (int i = 0; i < 4; i++) acc[mt][nt][i] = 0.f;

    gemm_issue(A, B, gsm, gsm + 128 * GAS, bRow, bCol, 0, K, N, tid);
    gemm_issue(A, B, gsm + GSTG, gsm + GSTG + 128 * GAS, bRow, bCol, 32, K, N, tid);

    const int iters = K / 32;
    for (int it = 0; it < iters; it++) {
        CPA_WAIT1();
        __syncthreads();
        float* As = gsm + (it & 1) * GSTG;
        float* Bs = As + 128 * GAS;
#pragma unroll
        for (int kk = 0; kk < 4; kk++) {
            unsigned a[4][4], bfr[4][2];
            const int kc = kk * 8 + (lane & 3);
            const int r0 = wr + (lane >> 2);
#pragma unroll
            for (int mt = 0; mt < 4; mt++) {
                a[mt][0] = __float_as_uint(As[(r0 + mt * 16) * GAS + kc]);
                a[mt][1] = __float_as_uint(As[(r0 + mt * 16 + 8) * GAS + kc]);
                a[mt][2] = __float_as_uint(As[(r0 + mt * 16) * GAS + kc + 4]);
                a[mt][3] = __float_as_uint(As[(r0 + mt * 16 + 8) * GAS + kc + 4]);
            }
            const int nc0 = wc + (lane >> 2);
#pragma unroll
            for (int nt = 0; nt < 4; nt++) {
                bfr[nt][0] = __float_as_uint(Bs[kc * GBS + nc0 + nt * 8]);
                bfr[nt][1] = __float_as_uint(Bs[(kc + 4) * GBS + nc0 + nt * 8]);
            }
#pragma unroll
            for (int mt = 0; mt < 4; mt++)
#pragma unroll
                for (int nt = 0; nt < 4; nt++)
                    mma8(acc[mt][nt], a[mt], bfr[nt]);
        }
        __syncthreads();
        if (it + 2 < iters) {
            float* As2 = gsm + (it & 1) * GSTG;
            gemm_issue(A, B, As2, As2 + 128 * GAS, bRow, bCol, (it + 2) * 32, K, N, tid);
        } else {
            CPA_COMMIT();
        }
    }
    const int r0 = bRow + wr + (lane >> 2);
    const int c0 = bCol + wc + 2 * (lane & 3);
#pragma unroll
    for (int mt = 0; mt < 4; mt++)
#pragma unroll
        for (int nt = 0; nt < 4; nt++) {
            float* p1 = C + (size_t)(r0 + mt * 16) * N + c0 + nt * 8;
            float* p2 = C + (size_t)(r0 + mt * 16 + 8) * N + c0 + nt * 8;
            *(float2*)p1 = make_float2(acc[mt][nt][0], acc[mt][nt][1]);
            *(float2*)p2 = make_float2(acc[mt][nt][2], acc[mt][nt][3]);
        }
}

// ---------------- activations: split q / k -----------------------------------
__global__ void __launch_bounds__(256) act_q_kernel()
{
    int wg = (blockIdx.x * 256 + threadIdx.x) >> 5;
    int lane = threadIdx.x & 31;
    float4 x = *(const float4*)(g_q + (size_t)wg * 128 + lane * 4);
    float m = fmaxf(fmaxf(x.x, x.y), fmaxf(x.z, x.w));
#pragma unroll
    for (int o = 16; o; o >>= 1) m = fmaxf(m, __shfl_xor_sync(~0u, m, o));
    float e0 = __expf(x.x - m), e1 = __expf(x.y - m), e2 = __expf(x.z - m), e3 = __expf(x.w - m);
    float s = e0 + e1 + e2 + e3;
#pragma unroll
    for (int o = 16; o; o >>= 1) s += __shfl_xor_sync(~0u, s, o);
    float inv = 1.f / s;
    *(float4*)(g_ql + (size_t)wg * 128 + lane * 4) = make_float4(e0 * inv, e1 * inv, e2 * inv, e3 * inv);
}

__global__ void __launch_bounds__(256) act_k_kernel()
{
    int rk = (blockIdx.x * 256 + threadIdx.x) >> 5;
    int lane = threadIdx.x & 31;
    float4 x = *(const float4*)(g_k + (size_t)rk * 128 + lane * 4);
    float m = fmaxf(fmaxf(x.x, x.y), fmaxf(x.z, x.w));
#pragma unroll
    for (int o = 16; o; o >>= 1) m = fmaxf(m, __shfl_xor_sync(~0u, m, o));
    float e0 = __expf(x.x - m), e1 = __expf(x.y - m), e2 = __expf(x.z - m), e3 = __expf(x.w - m);
    float s = e0 + e1 + e2 + e3;
#pragma unroll
    for (int o = 16; o; o >>= 1) s += __shfl_xor_sync(~0u, s, o);
    float inv = 1.f / s;
    *(float4*)(g_kl + (size_t)rk * 128 + lane * 4) = make_float4(e0 * inv, e1 * inv, e2 * inv, e3 * inv);
    float4 bt;
    bt.x = (fminf(x.x, 0.f) - log1pf(__expf(-fabsf(x.x)))) * 0.0625f;
    bt.y = (fminf(x.y, 0.f) - log1pf(__expf(-fabsf(x.y)))) * 0.0625f;
    bt.z = (fminf(x.z, 0.f) - log1pf(__expf(-fabsf(x.z)))) * 0.0625f;
    bt.w = (fminf(x.w, 0.f) - log1pf(__expf(-fabsf(x.w)))) * 0.0625f;
    *(float4*)(g_bt + (size_t)rk * 128 + lane * 4) = bt;
}

// ---------------- pairwise-dot (unchanged) ----------------------------------
__global__ void __launch_bounds__(256) pairdot_kernel(int isP)
{
    extern __shared__ float sm[];
    float* Xs = sm;
    float* Ys = sm + 8192;
    const int blk = blockIdx.x;
    const int tid = threadIdx.x;
    const float* xbase; const float* ybase; float* out; int ldx, ldy;
    if (isP) {
        int b = blk >> 8, h = (blk >> 4) & 15, cn = blk & 15;
        int tok0 = b * 1024 + cn * 64;
        xbase = g_ql + (size_t)tok0 * HIDN + h * 128; ldx = HIDN;
        ybase = g_kl + (size_t)tok0 * KVD + (h >> 2) * 128; ldy = KVD;
        out = g_P + (size_t)blk * 4096;
    } else {
        int b = blk >> 6, kv = (blk >> 4) & 3, cn = blk & 15;
        int tok0 = b * 1024 + cn * 64;
        xbase = g_kl + (size_t)tok0 * KVD + kv * 128; ldx = KVD;
        ybase = xbase; ldy = KVD;
        out = g_A + (size_t)blk * 4096;
    }
    for (int i = tid * 4; i < 8192; i += 1024) {
        int r = i >> 7, c = i & 127;
        *(float4*)(Xs + i) = *(const float4*)(xbase + (size_t)r * ldx + c);
        *(float4*)(Ys + i) = *(const float4*)(ybase + (size_t)r * ldy + c);
    }
    __syncthreads();
    const int a0 = (tid >> 4) * 4, b0 = (tid & 15) * 4;
    float s4[4][4];
#pragma unroll
    for (int i = 0; i < 4; i++)
#pragma unroll
        for (int j = 0; j < 4; j++) s4[i][j] = 0.f;
    for (int d = 0; d < 128; d += 4) {
        float4 qa[4], kb[4];
#pragma unroll
        for (int i = 0; i < 4; i++) qa[i] = *(const float4*)(Xs + (a0 + i) * 128 + d);
#pragma unroll
        for (int j = 0; j < 4; j++) kb[j] = *(const float4*)(Ys + (b0 + j) * 128 + d);
#pragma unroll
        for (int i = 0; i < 4; i++)
#pragma unroll
            for (int j = 0; j < 4; j++)
                s4[i][j] += qa[i].x * kb[j].x + qa[i].y * kb[j].y + qa[i].z * kb[j].z + qa[i].w * kb[j].w;
    }
#pragma unroll
    for (int i = 0; i < 4; i++)
#pragma unroll
        for (int j = 0; j < 4; j++) {
            int t = a0 + i, s = b0 + j;
            bool keep = isP ? (s <= t) : (s < t);
            out[t * 64 + s] = keep ? s4[i][j] : 0.f;
        }
}

// ---------------- M inverse precompute (unchanged) ---------------------------
__global__ void __launch_bounds__(128) minv_kernel()
{
    extern __shared__ float ms[];
    float* As = ms;
    float* Xs = ms + 4096;
    float* bs = Xs + 8320;
    const int tid = threadIdx.x;
    const int c0 = blockIdx.x * 2, ach = blockIdx.y;
    const int b = ach >> 6, kv = (ach >> 4) & 3, cn = ach & 15;
    const int tok0 = b * 1024 + cn * 64;

    for (int i = tid * 4; i < 4096; i += 512)
        *(float4*)(As + i) = *(const float4*)(g_A + (size_t)ach * 4096 + i);
    {
        int c = tid >> 6, t = tid & 63;
        bs[c * 64 + t] = g_bt[(size_t)(tok0 + t) * KVD + kv * 128 + c0 + c];
    }
    __syncthreads();

    const int c = tid >> 6, s = tid & 63;
    float* Xc = Xs + c * 4160;
    Xc[s * 65 + s] = 1.f;
    for (int i = s + 1; i < 64; i++) {
        float acc = 0.f;
        for (int p = s; p < i; p++) acc += As[i * 64 + p] * Xc[p * 65 + s];
        Xc[i * 65 + s] = -bs[c * 64 + i] * acc;
    }
    __nv_bfloat16* dst = g_M + (size_t)((ach * 128 + c0 + c) * 64) * 64 + s;
    for (int t = 0; t < 64; t++) {
        float val = (t > s) ? Xc[t * 65 + s] : (t == s ? 1.f : 0.f);
        dst[t * 64] = __float2bfloat16(val);
    }
}

// ---------------- flash attention (unchanged) ---------------------------------
#define FQS 132
#define FKS 132
#define FVS 136
#define FSS 68

__global__ void __launch_bounds__(256) flash_kernel(
    const float* __restrict__ q, const float* __restrict__ k,
    const float* __restrict__ v, float* __restrict__ comb)
{
    extern __shared__ float fsm[];
    float* Qs = fsm;
    float* Ks = Qs + 64 * FQS;
    float* Vs = Ks + 64 * FKS;
    float* Ss = Vs + 64 * FVS;
    float* msh = Ss + 64 * FSS;
    float* lsh = msh + 64;
    float* csh = lsh + 64;
    const int tid = threadIdx.x, lane = tid & 31, warp = tid >> 5;
    const int qt = 15 - (blockIdx.x & 15);
    const int bh = blockIdx.y;
    const int b = bh >> 4, h = bh & 15, kvh = h >> 2;
    const float scale = 0.08838834764831845f;
    {
        const float* qb = q + (size_t)(b * 1024 + qt * 64) * HIDN + h * 128;
        for (int i = tid; i < 2048; i += 256) {
            int r = i >> 5, c4 = (i & 31) * 4;
            float4 t4 = *(const float4*)(qb + (size_t)r * HIDN + c4);
            Qs[r * FQS + c4 + 0] = f2tf_f(t4.x * scale);
            Qs[r * FQS + c4 + 1] = f2tf_f(t4.y * scale);
            Qs[r * FQS + c4 + 2] = f2tf_f(t4.z * scale);
            Qs[r * FQS + c4 + 3] = f2tf_f(t4.w * scale);
        }
    }
    if (tid < 64) { msh[tid] = -1e30f; lsh[tid] = 0.f; }
    const int wr2 = (warp >> 2) * 32, wc2 = (warp & 3) * 32;
    float oc[2][4][4];
#pragma unroll
    for (int mt = 0; mt < 2; mt++)
#pragma unroll
        for (int nt = 0; nt < 4; nt++)
#pragma unroll
            for (int i = 0; i < 4; i++) oc[mt][nt][i] = 0.f;

    for (int j = 0; j <= qt; j++) {
        __syncthreads();
        {
            const float* kb = k + (size_t)(b * 1024 + j * 64) * KVD + kvh * 128;
            const float* vb = v + (size_t)(b * 1024 + j * 64) * KVD + kvh * 128;
            for (int i = tid; i < 2048; i += 256) {
                int r = i >> 5, c4 = (i & 31) * 4;
                float4 k4 = *(const float4*)(kb + (size_t)r * KVD + c4);
                Ks[r * FKS + c4 + 0] = f2tf_f(k4.x); Ks[r * FKS + c4 + 1] = f2tf_f(k4.y);
                Ks[r * FKS + c4 + 2] = f2tf_f(k4.z); Ks[r * FKS + c4 + 3] = f2tf_f(k4.w);
                float4 v4 = *(const float4*)(vb + (size_t)r * KVD + c4);
                Vs[r * FVS + c4 + 0] = f2tf_f(v4.x); Vs[r * FVS + c4 + 1] = f2tf_f(v4.y);
                Vs[r * FVS + c4 + 2] = f2tf_f(v4.z); Vs[r * FVS + c4 + 3] = f2tf_f(v4.w);
            }
        }
        __syncthreads();
        {
            float sc[2][2][4];
#pragma unroll
            for (int mt = 0; mt < 2; mt++)
#pragma unroll
                for (int nt = 0; nt < 2; nt++)
#pragma unroll
                    for (int i = 0; i < 4; i++) sc[mt][nt][i] = 0.f;
            const int swr = (warp >> 2) * 32, swc = (warp & 3) * 16;
            const int r0 = swr + (lane >> 2);
#pragma unroll
            for (int ks = 0; ks < 16; ks++) {
                const int kc = ks * 8 + (lane & 3);
                unsigned a[2][4], bf[2][2];
#pragma unroll
                for (int mt = 0; mt < 2; mt++) {
                    a[mt][0] = __float_as_uint(Qs[(r0 + mt * 16) * FQS + kc]);
                    a[mt][1] = __float_as_uint(Qs[(r0 + mt * 16 + 8) * FQS + kc]);
                    a[mt][2] = __float_as_uint(Qs[(r0 + mt * 16) * FQS + kc + 4]);
                    a[mt][3] = __float_as_uint(Qs[(r0 + mt * 16 + 8) * FQS + kc + 4]);
                }
                const int nc = swc + (lane >> 2);
#pragma unroll
                for (int nt = 0; nt < 2; nt++) {
                    bf[nt][0] = __float_as_uint(Ks[(nc + nt * 8) * FKS + kc]);
                    bf[nt][1] = __float_as_uint(Ks[(nc + nt * 8) * FKS + kc + 4]);
                }
#pragma unroll
                for (int mt = 0; mt < 2; mt++)
#pragma unroll
                    for (int nt = 0; nt < 2; nt++)
                        mma8(sc[mt][nt], a[mt], bf[nt]);
            }
#pragma unroll
            for (int mt = 0; mt < 2; mt++)
#pragma unroll
                for (int nt = 0; nt < 2; nt++) {
                    int rr = swr + mt * 16 + (lane >> 2);
                    int cc = swc + nt * 8 + 2 * (lane & 3);
                    Ss[rr * FSS + cc] = sc[mt][nt][0];
                    Ss[rr * FSS + cc + 1] = sc[mt][nt][1];
                    Ss[(rr + 8) * FSS + cc] = sc[mt][nt][2];
                    Ss[(rr + 8) * FSS + cc + 1] = sc[mt][nt][3];
                }
        }
        __syncthreads();
        {
            const int row = tid >> 2, sub = tid & 3;
            float* srow = Ss + row * FSS + sub * 16;
            float pv[16];
            float mx = -1e30f;
#pragma unroll
            for (int ii = 0; ii < 16; ii++) {
                float x = srow[ii];
                if (j == qt && (sub * 16 + ii) > row) x = -1e30f;
                pv[ii] = x;
                mx = fmaxf(mx, x);
            }
            mx = fmaxf(mx, __shfl_xor_sync(~0u, mx, 1));
            mx = fmaxf(mx, __shfl_xor_sync(~0u, mx, 2));
            float mold = msh[row];
            float mnew = fmaxf(mx, mold);
            float cf = __expf(mold - mnew);
            float lsum = 0.f;
#pragma unroll
            for (int ii = 0; ii < 16; ii++) {
                float p = __expf(pv[ii] - mnew);
                srow[ii] = f2tf_f(p);
                lsum += p;
            }
            lsum += __shfl_xor_sync(~0u, lsum, 1);
            lsum += __shfl_xor_sync(~0u, lsum, 2);
            if (sub == 0) {
                msh[row] = mnew;
                lsh[row] = lsh[row] * cf + lsum;
                csh[row] = cf;
            }
        }
        __syncthreads();
        {
            const int rA = wr2 + (lane >> 2);
#pragma unroll
            for (int mt = 0; mt < 2; mt++) {
                float cl = csh[rA + mt * 16];
                float ch = csh[rA + mt * 16 + 8];
#pragma unroll
                for (int nt = 0; nt < 4; nt++) {
                    oc[mt][nt][0] *= cl; oc[mt][nt][1] *= cl;
                    oc[mt][nt][2] *= ch; oc[mt][nt][3] *= ch;
                }
            }
#pragma unroll
            for (int ks = 0; ks < 8; ks++) {
                const int kc = ks * 8 + (lane & 3);
                unsigned a[2][4], bf[4][2];
#pragma unroll
                for (int mt = 0; mt < 2; mt++) {
                    a[mt][0] = __float_as_uint(Ss[(rA + mt * 16) * FSS + kc]);
                    a[mt][1] = __float_as_uint(Ss[(rA + mt * 16 + 8) * FSS + kc]);
                    a[mt][2] = __float_as_uint(Ss[(rA + mt * 16) * FSS + kc + 4]);
                    a[mt][3] = __float_as_uint(Ss[(rA + mt * 16 + 8) * FSS + kc + 4]);
                }
                const int nc = wc2 + (lane >> 2);
#pragma unroll
                for (int nt = 0; nt < 4; nt++) {
                    bf[nt][0] = __float_as_uint(Vs[kc * FVS + nc + nt * 8]);
                    bf[nt][1] = __float_as_uint(Vs[(kc + 4) * FVS + nc + nt * 8]);
                }
#pragma unroll
                for (int mt = 0; mt < 2; mt++)
#pragma unroll
                    for (int nt = 0; nt < 4; nt++)
                        mma8(oc[mt][nt], a[mt], bf[nt]);
            }
        }
    }
#pragma unroll
    for (int mt = 0; mt < 2; mt++) {
        int r1 = wr2 + mt * 16 + (lane >> 2);
        int r2 = r1 + 8;
        float il1 = 0.5f / lsh[r1];
        float il2 = 0.5f / lsh[r2];
        size_t base1 = (size_t)(b * 1024 + qt * 64 + r1) * HIDN + h * 128;
        size_t base2 = (size_t)(b * 1024 + qt * 64 + r2) * HIDN + h * 128;
#pragma unroll
        for (int nt = 0; nt < 4; nt++) {
            int col = wc2 + nt * 8 + 2 * (lane & 3);
            *(float2*)(comb + base1 + col) = make_float2(oc[mt][nt][0] * il1, oc[mt][nt][1] * il1);
            *(float2*)(comb + base2 + col) = make_float2(oc[mt][nt][2] * il2, oc[mt][nt][3] * il2);
        }
    }
}

// ---------------- delta-rule (unchanged from R14 winner) ----------------------
#define DSTG5 10880

__device__ __forceinline__ void delta_prefetch5(float* base, int gn, int c0, int tid)
{
    int bb = gn >> 8, hh = (gn >> 4) & 15, cn = gn & 15, kv = hh >> 2;
    int tok0 = bb * 1024 + cn * 64;
    int ach = (bb * 4 + kv) * 16 + cn;
    float* K_ = base;
    __nv_bfloat16* Mb = (__nv_bfloat16*)(base + 8448);
    float* v_ = base + 10752;
    float* b_ = base + 10816;
#pragma unroll
    for (int i = 0; i < 16; i++) {
        int jj = tid + 128 * i; int tr = jj >> 5, cc = (jj & 31) << 2;
        cpa16(K_ + tr * 132 + cc, g_kl + (size_t)(tok0 + tr) * KVD + kv * 128 + cc);
    }
#pragma unroll
    for (int i = 0; i < 4; i++) {
        int jj = tid + 128 * i; int row = jj >> 3, k8 = (jj & 7) * 8;
        cpa16(Mb + row * 72 + k8,
              g_M + ((size_t)(ach * 128 + c0) * 64 + row) * 64 + k8);
    }
    if (tid < 64) {
        cpa4(v_ + tid, g_v + (size_t)(tok0 + tid) * KVD + kv * 128 + c0);
    } else {
        int tt = tid - 64;
        cpa4(b_ + tt, g_bt + (size_t)(tok0 + tt) * KVD + kv * 128 + c0);
    }
}

__global__ void __launch_bounds__(128) delta_kernel()
{
    extern __shared__ float dsm[];
    float* Ssh = dsm + 3 * DSTG5;
    float* r_ = Ssh + 128;
    float* u_ = r_ + 68;
    const int tid = threadIdx.x;
    const int c0 = blockIdx.x;
    const int t = tid >> 1, hf = tid & 1;

    float sreg = 0.f;
    Ssh[tid] = 0.f;
    delta_prefetch5(dsm, 0, c0, tid);
    CPA_COMMIT();
    delta_prefetch5(dsm + DSTG5, 1, c0, tid);
    CPA_COMMIT();

    for (int gc = 0; gc < NGC; gc++) {
        if (gc + 2 < NGC)
            delta_prefetch5(dsm + ((gc + 2) % 3) * DSTG5, gc + 2, c0, tid);
        CPA_COMMIT();
        CPA_WAIT2();
        __syncthreads();

        float* base = dsm + (gc % 3) * DSTG5;
        float* K_ = base;
        const __nv_bfloat16* Mb = (const __nv_bfloat16*)(base + 8448);
        float* v_ = base + 10752;
        float* b_ = base + 10816;

        g_S0T[((size_t)gc * 128 + tid) * 128 + c0] = sreg;

        {
            float m0 = 0.f, m1 = 0.f, m2 = 0.f, m3 = 0.f;
            const float* krow = K_ + t * 132 + hf * 64;
            const float* scol = Ssh + hf * 64;
#pragma unroll
            for (int d = 0; d < 64; d += 4) {
                float4 k4 = *(const float4*)(krow + d);
                float4 s4 = *(const float4*)(scol + d);
                m0 += k4.x * s4.x; m1 += k4.y * s4.y;
                m2 += k4.z * s4.z; m3 += k4.w * s4.w;
            }
            float mm = (m0 + m1) + (m2 + m3);
            mm += __shfl_xor_sync(~0u, mm, 1);
            if (hf == 0) r_[t] = b_[t] * (v_[t] - mm);
        }
        __syncthreads();

        {
            float u0 = 0.f, u1 = 0.f, u2 = 0.f, u3 = 0.f;
            const __nv_bfloat16* mrow = Mb + t * 72 + hf * 32;
            const float* rr = r_ + hf * 32;
#pragma unroll
            for (int j = 0; j < 4; j++) {
                uint4 w = *(const uint4*)(mrow + j * 8);
                float2 f0 = __bfloat1622float2(*(__nv_bfloat162*)&w.x);
                float2 f1 = __bfloat1622float2(*(__nv_bfloat162*)&w.y);
                float2 f2 = __bfloat1622float2(*(__nv_bfloat162*)&w.z);
                float2 f3 = __bfloat1622float2(*(__nv_bfloat162*)&w.w);
                float4 ra = *(const float4*)(rr + j * 8);
                float4 rb = *(const float4*)(rr + j * 8 + 4);
                u0 += f0.x * ra.x + f0.y * ra.y;
                u1 += f1.x * ra.z + f1.y * ra.w;
                u2 += f2.x * rb.x + f2.y * rb.y;
                u3 += f3.x * rb.z + f3.y * rb.w;
            }
            float u = (u0 + u1) + (u2 + u3);
            u += __shfl_xor_sync(~0u, u, 1);
            if (hf == 0) {
                u_[t] = u;
                g_U[((size_t)gc * 64 + t) * 128 + c0] = u;
            }
        }
        __syncthreads();

        {
            float a0 = 0.f, a1 = 0.f, a2 = 0.f, a3 = 0.f;
#pragma unroll 4
            for (int t2 = 0; t2 < 64; t2 += 4) {
                a0 += K_[(t2 + 0) * 132 + tid] * u_[t2 + 0];
                a1 += K_[(t2 + 1) * 132 + tid] * u_[t2 + 1];
                a2 += K_[(t2 + 2) * 132 + tid] * u_[t2 + 2];
                a3 += K_[(t2 + 3) * 132 + tid] * u_[t2 + 3];
            }
            sreg += (a0 + a1) + (a2 + a3);
            Ssh[tid] = sreg;
        }
    }
}

// ---------------- okernel (unchanged) -----------------------------------------
__global__ void __launch_bounds__(256) okernel(float* __restrict__ comb)
{
    extern __shared__ float osm[];
    float* Qs = osm;
    float* Ps = Qs + 8448;
    float* Us = Ps + 4352;
    float* S0p = Us + 8448;
    const int gc = blockIdx.x;
    const int b = gc >> 8, h = (gc >> 4) & 15, cn = gc & 15;
    const int tok0 = b * 1024 + cn * 64;
    const int tid = threadIdx.x;

    for (int i = tid; i < 2048; i += 256) {
        int r = i >> 5, c4 = (i & 31) * 4;
        *(float4*)(Qs + r * 132 + c4) =
            *(const float4*)(g_ql + (size_t)(tok0 + r) * HIDN + h * 128 + c4);
    }
    for (int i = tid; i < 1024; i += 256) {
        int r = i >> 4, c4 = (i & 15) * 4;
        *(float4*)(Ps + r * 68 + c4) = *(const float4*)(g_P + (size_t)gc * 4096 + i * 4);
    }
    for (int i = tid; i < 2048; i += 256) {
        int s = i >> 5, c4 = (i & 31) * 4;
        *(float4*)(Us + s * 132 + c4) = *(const float4*)(g_U + ((size_t)gc * 64 + s) * 128 + c4);
    }
    __syncthreads();

    const int t0 = (tid >> 4) * 4, cc0 = (tid & 15) * 8;
    float acc[4][8];
#pragma unroll
    for (int i = 0; i < 4; i++)
#pragma unroll
        for (int j = 0; j < 8; j++) acc[i][j] = 0.f;
    for (int s = 0; s < 64; s++) {
        float4 ua = *(const float4*)(Us + s * 132 + cc0);
        float4 ub = *(const float4*)(Us + s * 132 + cc0 + 4);
#pragma unroll
        for (int i = 0; i < 4; i++) {
            float p = Ps[(t0 + i) * 68 + s];
            acc[i][0] += p * ua.x; acc[i][1] += p * ua.y;
            acc[i][2] += p * ua.z; acc[i][3] += p * ua.w;
            acc[i][4] += p * ub.x; acc[i][5] += p * ub.y;
            acc[i][6] += p * ub.z; acc[i][7] += p * ub.w;
        }
    }
    for (int kp = 0; kp < 128; kp += 32) {
        __syncthreads();
        for (int i = tid; i < 1024; i += 256) {
            int k = i >> 5, c4 = (i & 31) * 4;
            *(float4*)(S0p + k * 132 + c4) =
                *(const float4*)(g_S0T + ((size_t)gc * 128 + kp + k) * 128 + c4);
        }
        __syncthreads();
        for (int k = 0; k < 32; k++) {
            float4 sa = *(const float4*)(S0p + k * 132 + cc0);
            float4 sb = *(const float4*)(S0p + k * 132 + cc0 + 4);
#pragma unroll
            for (int i = 0; i < 4; i++) {
                float qv = Qs[(t0 + i) * 132 + kp + k];
                acc[i][0] += qv * sa.x; acc[i][1] += qv * sa.y;
                acc[i][2] += qv * sa.z; acc[i][3] += qv * sa.w;
                acc[i][4] += qv * sb.x; acc[i][5] += qv * sb.y;
                acc[i][6] += qv * sb.z; acc[i][7] += qv * sb.w;
            }
        }
    }
#pragma unroll
    for (int i = 0; i < 4; i++) {
        float* dst = comb + (size_t)(tok0 + t0 + i) * HIDN + h * 128 + cc0;
        float4 o1 = *(float4*)dst;
        float4 o2 = *(float4*)(dst + 4);
        o1.x = f2tf_f(o1.x + 0.5f * acc[i][0]); o1.y = f2tf_f(o1.y + 0.5f * acc[i][1]);
        o1.z = f2tf_f(o1.z + 0.5f * acc[i][2]); o1.w = f2tf_f(o1.w + 0.5f * acc[i][3]);
        o2.x = f2tf_f(o2.x + 0.5f * acc[i][4]); o2.y = f2tf_f(o2.y + 0.5f * acc[i][5]);
        o2.z = f2tf_f(o2.z + 0.5f * acc[i][6]); o2.w = f2tf_f(o2.w + 0.5f * acc[i][7]);
        *(float4*)dst = o1; *(float4*)(dst + 4) = o2;
    }
}

// ---------------- launch -----------------------------------------------------
extern "C" void kernel_launch(void* const* d_in, const int* in_sizes, int n_in,
                              void* d_out, int out_size)
{
    const float* hs = (const float*)d_in[0];
    const float* Wq = (const float*)d_in[1];
    const float* Wk = (const float*)d_in[2];
    const float* Wv = (const float*)d_in[3];
    const float* Wo = (const float*)d_in[4];
    float* out = (float*)d_out;

    float *p_q, *p_k, *p_v, *p_comb;
    float *p_hsr, *p_wqr, *p_wkr, *p_wvr, *p_wor;
    cudaGetSymbolAddress((void**)&p_q, g_q);
    cudaGetSymbolAddress((void**)&p_k, g_k);
    cudaGetSymbolAddress((void**)&p_v, g_v);
    cudaGetSymbolAddress((void**)&p_comb, g_comb);
    cudaGetSymbolAddress((void**)&p_hsr, g_hsr);
    cudaGetSymbolAddress((void**)&p_wqr, g_wqr);
    cudaGetSymbolAddress((void**)&p_wkr, g_wkr);
    cudaGetSymbolAddress((void**)&p_wvr, g_wvr);
    cudaGetSymbolAddress((void**)&p_wor, g_wor);

    static cudaStream_t s2 = nullptr;
    static cudaEvent_t evH = nullptr, evKV = nullptr, evAK = nullptr, evP2 = nullptr;
    if (!s2) {
        cudaStreamCreateWithFlags(&s2, cudaStreamNonBlocking);
        cudaEventCreateWithFlags(&evH, cudaEventDisableTiming);
        cudaEventCreateWithFlags(&evKV, cudaEventDisableTiming);
        cudaEventCreateWithFlags(&evAK, cudaEventDisableTiming);
        cudaEventCreateWithFlags(&evP2, cudaEventDisableTiming);
    }

    const int gemm_smem = 2 * GSTG * 4;
    const int pair_smem = 8192 * 2 * 4;
    const int flash_smem = (64 * FQS + 64 * FKS + 64 * FVS + 64 * FSS + 192) * 4;
    const int delta_smem = (3 * DSTG5 + 128 + 68 + 68) * 4;
    const int minv_smem = (4096 + 8320 + 128) * 4;
    const int o_smem = (8448 + 4352 + 8448 + 32 * 132) * 4;
    cudaFuncSetAttribute(mma_gemm, cudaFuncAttributeMaxDynamicSharedMemorySize, gemm_smem);
    cudaFuncSetAttribute(pairdot_kernel, cudaFuncAttributeMaxDynamicSharedMemorySize, pair_smem);
    cudaFuncSetAttribute(flash_kernel, cudaFuncAttributeMaxDynamicSharedMemorySize, flash_smem);
    cudaFuncSetAttribute(delta_kernel, cudaFuncAttributeMaxDynamicSharedMemorySize, delta_smem);
    cudaFuncSetAttribute(minv_kernel, cudaFuncAttributeMaxDynamicSharedMemorySize, minv_smem);
    cudaFuncSetAttribute(okernel, cudaFuncAttributeMaxDynamicSharedMemorySize, o_smem);

    // ---- s0: critical chain (delta-feeding) ----
    round_kernel<<<(TOK * HIDN / 4 + 255) / 256, 256>>>(hs, p_hsr, TOK * HIDN / 4);
    cudaEventRecord(evH, 0);
    round_kernel<<<(HIDN * KVD / 4 + 255) / 256, 256>>>(Wk, p_wkr, HIDN * KVD / 4);
    round_kernel<<<(HIDN * KVD / 4 + 255) / 256, 256>>>(Wv, p_wvr, HIDN * KVD / 4);
    mma_gemm<<<dim3(4, 16), 256, gemm_smem>>>(p_hsr, p_wkr, p_k, TOK, KVD, HIDN);
    mma_gemm<<<dim3(4, 16), 256, gemm_smem>>>(p_hsr, p_wvr, p_v, TOK, KVD, HIDN);
    cudaEventRecord(evKV, 0);
    act_k_kernel<<<1024, 256>>>();
    cudaEventRecord(evAK, 0);
    pairdot_kernel<<<NACH, 256, pair_smem>>>(0);
    minv_kernel<<<dim3(64, 128), 128, minv_smem>>>();
    delta_kernel<<<128, 128, delta_smem>>>();

    // ---- s2: Q-side + flash + pairdotP ----
    cudaStreamWaitEvent(s2, evH, 0);
    round_kernel<<<(HIDN * HIDN / 4 + 255) / 256, 256, 0, s2>>>(Wq, p_wqr, HIDN * HIDN / 4);
    round_kernel<<<(HIDN * HIDN / 4 + 255) / 256, 256, 0, s2>>>(Wo, p_wor, HIDN * HIDN / 4);
    mma_gemm<<<dim3(16, 16), 256, gemm_smem, s2>>>(p_hsr, p_wqr, p_q, TOK, HIDN, HIDN);
    act_q_kernel<<<4096, 256, 0, s2>>>();
    cudaStreamWaitEvent(s2, evKV, 0);
    flash_kernel<<<dim3(16, 32), 256, flash_smem, s2>>>(p_q, p_k, p_v, p_comb);
    cudaStreamWaitEvent(s2, evAK, 0);
    pairdot_kernel<<<NGC, 256, pair_smem, s2>>>(1);
    cudaEventRecord(evP2, s2);

    // ---- join on s0 ----
    cudaStreamWaitEvent(0, evP2, 0);
    okernel<<<NGC, 256, o_smem>>>(p_comb);
    mma_gemm<<<dim3(16, 16), 256, gemm_smem>>>(p_comb, p_wor, out, TOK, HIDN, HIDN);
}